// round 15
// baseline (speedup 1.0000x reference)
#include <cuda_runtime.h>
#include <cuda_fp16.h>
#include <math.h>
#include <cstdint>

// ---------------- problem constants ----------------
#define Bc   8
#define Sc   512
#define Dc   512
#define NHc  8
#define DHc  64
#define Lc   6
#define HIDc 2048
#define EPSc 1e-5f
#define BSc  (Bc * Sc)          // 4096 tokens
#define SCALEc 0.125f           // 1/sqrt(64)

// ---------------- device scratch ----------------
__device__ float  g_x[BSc * Dc];
__device__ float  g_y[BSc * Dc];
__device__ float  g_tmp[BSc * Dc];
__device__ __half g_xh[BSc * Dc];
__device__ __half g_yh[BSc * Dc];
__device__ __half g_qkvh[BSc * 3 * Dc];
__device__ __half g_qh[BSc * Dc];
__device__ __half g_attnh[BSc * Dc];
__device__ __half g_hidh[BSc * HIDc];
__device__ __half g_kvh[(size_t)Lc * BSc * 2 * Dc];   // all-layer cross KV cache
__device__ unsigned char g_mx[BSc];
__device__ unsigned char g_my[BSc];
// transposed fp16 weights: [N][K]
__device__ __half g_wt_enc_attn[Lc * 4 * Dc * Dc];
__device__ __half g_wt_dec_self[Lc * 4 * Dc * Dc];
__device__ __half g_wt_dec_cross[Lc * 4 * Dc * Dc];
__device__ __half g_wt_enc_f1[Lc * Dc * HIDc];
__device__ __half g_wt_enc_f2[Lc * Dc * HIDc];
__device__ __half g_wt_dec_f1[Lc * Dc * HIDc];
__device__ __half g_wt_dec_f2[Lc * Dc * HIDc];

__device__ __forceinline__ float neg_inf_f() { return __int_as_float(0xff800000u); }

__device__ __forceinline__ uint32_t smem_u32(const void* p) {
    uint32_t a;
    asm("{ .reg .u64 t; cvta.to.shared.u64 t, %1; cvt.u32.u64 %0, t; }" : "=r"(a) : "l"(p));
    return a;
}
__device__ __forceinline__ uint32_t pack_h2(float2 f) {
    __half2 h = __floats2half2_rn(f.x, f.y);
    return *reinterpret_cast<uint32_t*>(&h);
}

__device__ __forceinline__ void mma_16n8k16_f16(float c[4], const uint32_t a[4], const uint32_t b[2]) {
    asm volatile(
        "mma.sync.aligned.m16n8k16.row.col.f32.f16.f16.f32 "
        "{%0,%1,%2,%3}, {%4,%5,%6,%7}, {%8,%9}, {%0,%1,%2,%3};"
        : "+f"(c[0]), "+f"(c[1]), "+f"(c[2]), "+f"(c[3])
        : "r"(a[0]), "r"(a[1]), "r"(a[2]), "r"(a[3]), "r"(b[0]), "r"(b[1]));
}
#define LDSM4(r0, r1, r2, r3, addr) \
    asm volatile("ldmatrix.sync.aligned.m8n8.x4.shared.b16 {%0,%1,%2,%3}, [%4];" \
        : "=r"(r0), "=r"(r1), "=r"(r2), "=r"(r3) : "r"(addr))
#define LDSM4T(r0, r1, r2, r3, addr) \
    asm volatile("ldmatrix.sync.aligned.m8n8.x4.trans.shared.b16 {%0,%1,%2,%3}, [%4];" \
        : "=r"(r0), "=r"(r1), "=r"(r2), "=r"(r3) : "r"(addr))

// ---------------- weight transpose (fp32 -> fp16) ----------------
__global__ void transpose_h(const float* __restrict__ in, __half* __restrict__ out,
                            int R, int C) {
    __shared__ float tile[32][33];
    const float* src = in + (size_t)blockIdx.z * R * C;
    __half* dst = out + (size_t)blockIdx.z * R * C;
    int c0 = blockIdx.x * 32, r0 = blockIdx.y * 32;
    int tx = threadIdx.x, ty = threadIdx.y;
    #pragma unroll
    for (int i = 0; i < 32; i += 8)
        tile[ty + i][tx] = src[(size_t)(r0 + ty + i) * C + c0 + tx];
    __syncthreads();
    #pragma unroll
    for (int i = 0; i < 32; i += 8)
        dst[(size_t)(c0 + ty + i) * R + r0 + tx] = __float2half_rn(tile[tx][ty + i]);
}

// ---------------- fp16 mma GEMM, K-chunk 64, 3-stage cp.async ring ----------------
// MT = CTA M-tile (64 or 128). CTA N-tile always 128. threads = 2*MT.
// MT=128: 8 warps (2M x 4N). MT=64: 4 warps (1M x 4N). Warp tile 64x32 both.
// Row stride 36 words: 36*{0..7} mod 32 all-distinct -> conflict-free LDSM.
#define GPAD 36
#define BBUFW (128 * GPAD)                              // B tile words
#define STG_W(MT)   ((MT) * GPAD + BBUFW)               // stage words
#define GEMM_SMEM_MT(MT) (3 * STG_W(MT) * 4)            // 3 stages
#define GEMM_SMEM   GEMM_SMEM_MT(128)                   // 110592 B
#define GEMM_SMEM64 GEMM_SMEM_MT(64)                    // 82944 B

template<bool RELU, bool HALFOUT, int MT>
__device__ __forceinline__ void gemm_body(const __half* A, const __half* BT,
                                          const float* bias, const float* resid,
                                          void* Cout, int row0, int col0, int N, int K,
                                          uint32_t* gs, uint32_t sbase) {
    const int T = 2 * MT;                 // threads
    const int ABUFW = MT * GPAD;
    const int STGW = ABUFW + BBUFW;
    int tid = threadIdx.x;
    int lane = tid & 31, wid = tid >> 5;
    int wm = (MT == 128) ? (wid & 1) : 0;
    int wn = (MT == 128) ? (wid >> 1) : wid;
    int g = lane >> 2, tg = lane & 3;
    int lrow = lane & 7, lj = lane >> 3;

    uint32_t a_off[4];
    #pragma unroll
    for (int mi = 0; mi < 4; mi++)
        a_off[mi] = (uint32_t)(((wm * 64 + mi * 16 + (lj & 1) * 8 + lrow) * GPAD
                                + (lj >> 1) * 4) * 4);
    uint32_t b_off[2];
    #pragma unroll
    for (int pr = 0; pr < 2; pr++)
        b_off[pr] = (uint32_t)(ABUFW * 4
                    + ((wn * 32 + pr * 16 + (lane >> 4) * 8 + lrow) * GPAD
                       + ((lane >> 3) & 1) * 4) * 4);

    float acc[4][4][4];
    #pragma unroll
    for (int mi = 0; mi < 4; mi++)
        #pragma unroll
        for (int ni = 0; ni < 4; ni++)
            #pragma unroll
            for (int r = 0; r < 4; r++) acc[mi][ni][r] = 0.0f;

    int nch = K >> 6;

    {   // prefetch chunk 0 into stage 0
        uint32_t ab = sbase, bb = sbase + ABUFW * 4;
        #pragma unroll
        for (int i = 0; i < (MT * 8) / (2 * MT); ++i) {        // 4 passes
            int idx = tid + i * T;
            int n = idx >> 3, ch = idx & 7;
            const __half* pa = &A[(size_t)(row0 + n) * K + ch * 8];
            asm volatile("cp.async.cg.shared.global [%0], [%1], 16;"
                         :: "r"(ab + (uint32_t)(n * GPAD + ch * 4) * 4), "l"(pa));
        }
        #pragma unroll
        for (int i = 0; i < 1024 / (2 * MT); ++i) {            // 4 or 8 passes
            int idx = tid + i * T;
            int n = idx >> 3, ch = idx & 7;
            const __half* pb = &BT[(size_t)(col0 + n) * K + ch * 8];
            asm volatile("cp.async.cg.shared.global [%0], [%1], 16;"
                         :: "r"(bb + (uint32_t)(n * GPAD + ch * 4) * 4), "l"(pb));
        }
        asm volatile("cp.async.commit_group;" ::: "memory");
    }

    for (int c = 0; c < nch; ++c) {
        if (c + 1 < nch) {
            int k0 = (c + 1) << 6;
            uint32_t stoff = (uint32_t)(((c + 1) % 3) * STGW) * 4;
            uint32_t ab = sbase + stoff, bb = ab + ABUFW * 4;
            #pragma unroll
            for (int i = 0; i < (MT * 8) / (2 * MT); ++i) {
                int idx = tid + i * T;
                int n = idx >> 3, ch = idx & 7;
                const __half* pa = &A[(size_t)(row0 + n) * K + k0 + ch * 8];
                asm volatile("cp.async.cg.shared.global [%0], [%1], 16;"
                             :: "r"(ab + (uint32_t)(n * GPAD + ch * 4) * 4), "l"(pa));
            }
            #pragma unroll
            for (int i = 0; i < 1024 / (2 * MT); ++i) {
                int idx = tid + i * T;
                int n = idx >> 3, ch = idx & 7;
                const __half* pb = &BT[(size_t)(col0 + n) * K + k0 + ch * 8];
                asm volatile("cp.async.cg.shared.global [%0], [%1], 16;"
                             :: "r"(bb + (uint32_t)(n * GPAD + ch * 4) * 4), "l"(pb));
            }
        }
        asm volatile("cp.async.commit_group;" ::: "memory");
        asm volatile("cp.async.wait_group 1;" ::: "memory");
        __syncthreads();

        uint32_t stb = sbase + (uint32_t)((c % 3) * STGW) * 4;

        #pragma unroll
        for (int ki = 0; ki < 4; ++ki) {
            uint32_t ko = (uint32_t)ki * 32;
            uint32_t afr[4][4];
            #pragma unroll
            for (int mi = 0; mi < 4; mi++)
                LDSM4(afr[mi][0], afr[mi][1], afr[mi][2], afr[mi][3], stb + a_off[mi] + ko);
            uint32_t bfr[4][2];
            {
                uint32_t t0, t1, t2, t3;
                LDSM4(t0, t1, t2, t3, stb + b_off[0] + ko);
                bfr[0][0] = t0; bfr[0][1] = t1; bfr[1][0] = t2; bfr[1][1] = t3;
                LDSM4(t0, t1, t2, t3, stb + b_off[1] + ko);
                bfr[2][0] = t0; bfr[2][1] = t1; bfr[3][0] = t2; bfr[3][1] = t3;
            }
            #pragma unroll
            for (int mi = 0; mi < 4; mi++)
                #pragma unroll
                for (int ni = 0; ni < 4; ni++)
                    mma_16n8k16_f16(acc[mi][ni], afr[mi], bfr[ni]);
        }
    }

    #pragma unroll
    for (int mi = 0; mi < 4; mi++) {
        int r0r = row0 + wm * 64 + mi * 16 + g;
        #pragma unroll
        for (int ni = 0; ni < 4; ni++) {
            int cb = col0 + wn * 32 + ni * 8 + tg * 2;
            float b0 = bias[cb], b1 = bias[cb + 1];
            float v0 = acc[mi][ni][0] + b0, v1 = acc[mi][ni][1] + b1;
            float v2 = acc[mi][ni][2] + b0, v3 = acc[mi][ni][3] + b1;
            if (resid) {
                float2 r0v = *reinterpret_cast<const float2*>(&resid[(size_t)(r0r)     * N + cb]);
                float2 r1v = *reinterpret_cast<const float2*>(&resid[(size_t)(r0r + 8) * N + cb]);
                v0 += r0v.x; v1 += r0v.y; v2 += r1v.x; v3 += r1v.y;
            }
            if (RELU) { v0 = fmaxf(v0, 0.f); v1 = fmaxf(v1, 0.f);
                        v2 = fmaxf(v2, 0.f); v3 = fmaxf(v3, 0.f); }
            if (HALFOUT) {
                __half* Ch = (__half*)Cout;
                *reinterpret_cast<uint32_t*>(&Ch[(size_t)(r0r)     * N + cb]) = pack_h2(make_float2(v0, v1));
                *reinterpret_cast<uint32_t*>(&Ch[(size_t)(r0r + 8) * N + cb]) = pack_h2(make_float2(v2, v3));
            } else {
                float* Cf = (float*)Cout;
                *reinterpret_cast<float2*>(&Cf[(size_t)(r0r)     * N + cb]) = make_float2(v0, v1);
                *reinterpret_cast<float2*>(&Cf[(size_t)(r0r + 8) * N + cb]) = make_float2(v2, v3);
            }
        }
    }
}

template<bool RELU, bool HALFOUT>
__global__ void __launch_bounds__(256) gemm_mma(const __half* __restrict__ A,
                                                const __half* __restrict__ BT,
                                                const float* __restrict__ bias,
                                                const float* __restrict__ resid,
                                                void* __restrict__ Cout,
                                                int M, int N, int K) {
    extern __shared__ uint32_t gs[];
    gemm_body<RELU, HALFOUT, 128>(A, BT, bias, resid, Cout,
                                  blockIdx.y * 128, blockIdx.x * 128, N, K, gs, smem_u32(gs));
}
// M-tile 64 variant (128 threads): doubles CTA count for N=512 GEMMs -> fills chip.
template<bool RELU, bool HALFOUT>
__global__ void __launch_bounds__(128) gemm_mma64(const __half* __restrict__ A,
                                                  const __half* __restrict__ BT,
                                                  const float* __restrict__ bias,
                                                  const float* __restrict__ resid,
                                                  void* __restrict__ Cout,
                                                  int M, int N, int K) {
    extern __shared__ uint32_t gs[];
    gemm_body<RELU, HALFOUT, 64>(A, BT, bias, resid, Cout,
                                 blockIdx.y * 64, blockIdx.x * 128, N, K, gs, smem_u32(gs));
}

// batched cross-attn KV projection for ALL layers: z = layer.
__global__ void __launch_bounds__(256) gemm_kv_all(const __half* __restrict__ A,
                                                   const __half* __restrict__ wbase,
                                                   const float* __restrict__ bbase,
                                                   __half* __restrict__ Cbase) {
    extern __shared__ uint32_t gs[];
    int l = blockIdx.z;
    const __half* BT = wbase + (size_t)l * 4 * Dc * Dc + (size_t)Dc * Dc;
    const float* bias = bbase + (size_t)l * 4 * Dc + Dc;
    __half* C = Cbase + (size_t)l * BSc * 2 * Dc;
    gemm_body<false, true, 128>(A, BT, bias, nullptr, C,
                                blockIdx.y * 128, blockIdx.x * 128, 2 * Dc, Dc, gs, smem_u32(gs));
}

// ---------------- fused flash attention: q-tile 64, 128 threads ----------------
#define FW 36
#define FLASH_SMEM ((64 + 64 + 64) * FW * 4 + 64)

__global__ void __launch_bounds__(128) flash_attn(
    const __half* __restrict__ q, int ldq,
    const __half* __restrict__ k, const __half* __restrict__ v, int ldkv,
    const unsigned char* __restrict__ mqg, const unsigned char* __restrict__ mkg,
    __half* __restrict__ o, int causal)
{
    extern __shared__ char sm[];
    uint32_t smb = smem_u32(sm);
    uint32_t* Qs = reinterpret_cast<uint32_t*>(sm);
    uint32_t* Ks = Qs + 64 * FW;
    uint32_t* Vs = Ks + 64 * FW;
    unsigned char* mks = reinterpret_cast<unsigned char*>(Vs + 64 * FW);
    const uint32_t QS0 = 0, KS0 = 64 * FW * 4, VS0 = 128 * FW * 4;

    int tid = threadIdx.x, lane = tid & 31, wid = tid >> 5;
    int bh = blockIdx.y, b = bh >> 3, h = bh & 7;
    int qt = causal ? ((int)gridDim.x - 1 - (int)blockIdx.x) : (int)blockIdx.x;
    int q0 = qt * 64;
    const __half* Qg = q + (size_t)b * Sc * ldq + h * DHc;
    const __half* Kg = k + (size_t)b * Sc * ldkv + h * DHc;
    const __half* Vg = v + (size_t)b * Sc * ldkv + h * DHc;
    int g = lane >> 2, tg = lane & 3;
    int lrow = lane & 7, lj = lane >> 3;
    int rg = wid * 16 + g;
    int qi0 = q0 + rg, qi1 = qi0 + 8;

    uint32_t q_off = QS0 + (uint32_t)(((wid * 16 + (lj & 1) * 8 + lrow) * FW + (lj >> 1) * 4) * 4);
    uint32_t k_off[4];
    #pragma unroll
    for (int pr = 0; pr < 4; pr++)
        k_off[pr] = KS0 + (uint32_t)(((pr * 16 + (lane >> 4) * 8 + lrow) * FW
                                      + ((lane >> 3) & 1) * 4) * 4);
    uint32_t v_off[4];
    #pragma unroll
    for (int pr = 0; pr < 4; pr++)
        v_off[pr] = VS0 + (uint32_t)(((((lane >> 3) & 1) * 8 + lrow) * FW
                                      + (2 * pr + (lane >> 4)) * 4) * 4);

    #pragma unroll
    for (int i = 0; i < 4; ++i) {
        int idx = tid + i * 128;
        int r = idx >> 3, c8 = idx & 7;
        uint4 w = *reinterpret_cast<const uint4*>(&Qg[(size_t)(q0 + r) * ldq + c8 * 8]);
        *reinterpret_cast<uint4*>(&Qs[r * FW + c8 * 4]) = w;
    }
    bool mrow0 = mqg[b * Sc + qi0] != 0;
    bool mrow1 = mqg[b * Sc + qi1] != 0;

    float m0 = -1e30f, m1 = -1e30f, l0 = 0.f, l1 = 0.f;
    float oacc[8][4];
    #pragma unroll
    for (int ni = 0; ni < 8; ni++) { oacc[ni][0] = oacc[ni][1] = oacc[ni][2] = oacc[ni][3] = 0.f; }

    int nkt = causal ? ((q0 >> 6) + 1) : (Sc / 64);
    for (int kt = 0; kt < nkt; ++kt) {
        int k0 = kt * 64;
        __syncthreads();
        #pragma unroll
        for (int i = 0; i < 4; ++i) {
            int idx = tid + i * 128;
            int r = idx >> 3, c8 = idx & 7;
            uint4 wk = *reinterpret_cast<const uint4*>(&Kg[(size_t)(k0 + r) * ldkv + c8 * 8]);
            *reinterpret_cast<uint4*>(&Ks[r * FW + c8 * 4]) = wk;
            uint4 wv = *reinterpret_cast<const uint4*>(&Vg[(size_t)(k0 + r) * ldkv + c8 * 8]);
            *reinterpret_cast<uint4*>(&Vs[r * FW + c8 * 4]) = wv;
        }
        if (tid < 64) mks[tid] = mkg[b * Sc + k0 + tid];
        __syncthreads();

        float s[8][4];
        #pragma unroll
        for (int ni = 0; ni < 8; ni++) { s[ni][0] = s[ni][1] = s[ni][2] = s[ni][3] = 0.f; }
        #pragma unroll
        for (int ki = 0; ki < 4; ++ki) {
            uint32_t ko = (uint32_t)ki * 32;
            uint32_t a[4];
            LDSM4(a[0], a[1], a[2], a[3], smb + q_off + ko);
            uint32_t bfr[8][2];
            #pragma unroll
            for (int pr = 0; pr < 4; pr++) {
                uint32_t t0, t1, t2, t3;
                LDSM4(t0, t1, t2, t3, smb + k_off[pr] + ko);
                bfr[2 * pr][0] = t0; bfr[2 * pr][1] = t1;
                bfr[2 * pr + 1][0] = t2; bfr[2 * pr + 1][1] = t3;
            }
            #pragma unroll
            for (int ni = 0; ni < 8; ni++)
                mma_16n8k16_f16(s[ni], a, bfr[ni]);
        }

        float rmax0 = neg_inf_f(), rmax1 = neg_inf_f();
        #pragma unroll
        for (int ni = 0; ni < 8; ni++) {
            int cloc = ni * 8 + 2 * tg;
            int cg = k0 + cloc;
            bool mkA = mks[cloc] != 0, mkB = mks[cloc + 1] != 0;
            float v0 = (mrow0 || mkA || (causal && cg     > qi0)) ? neg_inf_f() : s[ni][0] * SCALEc;
            float v1 = (mrow0 || mkB || (causal && cg + 1 > qi0)) ? neg_inf_f() : s[ni][1] * SCALEc;
            float v2 = (mrow1 || mkA || (causal && cg     > qi1)) ? neg_inf_f() : s[ni][2] * SCALEc;
            float v3 = (mrow1 || mkB || (causal && cg + 1 > qi1)) ? neg_inf_f() : s[ni][3] * SCALEc;
            s[ni][0] = v0; s[ni][1] = v1; s[ni][2] = v2; s[ni][3] = v3;
            rmax0 = fmaxf(rmax0, fmaxf(v0, v1));
            rmax1 = fmaxf(rmax1, fmaxf(v2, v3));
        }
        rmax0 = fmaxf(rmax0, __shfl_xor_sync(0xffffffffu, rmax0, 1));
        rmax0 = fmaxf(rmax0, __shfl_xor_sync(0xffffffffu, rmax0, 2));
        rmax1 = fmaxf(rmax1, __shfl_xor_sync(0xffffffffu, rmax1, 1));
        rmax1 = fmaxf(rmax1, __shfl_xor_sync(0xffffffffu, rmax1, 2));

        float mn0 = fmaxf(m0, rmax0), mn1 = fmaxf(m1, rmax1);
        float sc0 = __expf(m0 - mn0), sc1 = __expf(m1 - mn1);
        float rs0 = 0.f, rs1 = 0.f;
        uint32_t pp[8][2];
        #pragma unroll
        for (int ni = 0; ni < 8; ni++) {
            float p0 = __expf(s[ni][0] - mn0), p1 = __expf(s[ni][1] - mn0);
            float p2 = __expf(s[ni][2] - mn1), p3 = __expf(s[ni][3] - mn1);
            rs0 += p0 + p1; rs1 += p2 + p3;
            pp[ni][0] = pack_h2(make_float2(p0, p1));
            pp[ni][1] = pack_h2(make_float2(p2, p3));
        }
        rs0 += __shfl_xor_sync(0xffffffffu, rs0, 1);
        rs0 += __shfl_xor_sync(0xffffffffu, rs0, 2);
        rs1 += __shfl_xor_sync(0xffffffffu, rs1, 1);
        rs1 += __shfl_xor_sync(0xffffffffu, rs1, 2);
        l0 = l0 * sc0 + rs0; l1 = l1 * sc1 + rs1;
        m0 = mn0; m1 = mn1;
        #pragma unroll
        for (int ni = 0; ni < 8; ni++) {
            oacc[ni][0] *= sc0; oacc[ni][1] *= sc0;
            oacc[ni][2] *= sc1; oacc[ni][3] *= sc1;
        }

        #pragma unroll
        for (int ki = 0; ki < 4; ++ki) {
            uint32_t vko = (uint32_t)ki * 16 * FW * 4;
            uint32_t a[4] = { pp[2 * ki][0], pp[2 * ki][1],
                              pp[2 * ki + 1][0], pp[2 * ki + 1][1] };
            uint32_t bfr[8][2];
            #pragma unroll
            for (int pr = 0; pr < 4; pr++) {
                uint32_t t0, t1, t2, t3;
                LDSM4T(t0, t1, t2, t3, smb + v_off[pr] + vko);
                bfr[2 * pr][0] = t0; bfr[2 * pr][1] = t1;
                bfr[2 * pr + 1][0] = t2; bfr[2 * pr + 1][1] = t3;
            }
            #pragma unroll
            for (int ni = 0; ni < 8; ni++)
                mma_16n8k16_f16(oacc[ni], a, bfr[ni]);
        }
    }

    float inv0 = (l0 > 0.f) ? 1.f / l0 : 0.f;
    float inv1 = (l1 > 0.f) ? 1.f / l1 : 0.f;
    size_t ob0 = ((size_t)b * Sc + qi0) * Dc + h * DHc;
    size_t ob1 = ((size_t)b * Sc + qi1) * Dc + h * DHc;
    #pragma unroll
    for (int ni = 0; ni < 8; ni++) {
        int cc = ni * 8 + 2 * tg;
        *reinterpret_cast<uint32_t*>(&o[ob0 + cc]) =
            pack_h2(make_float2(oacc[ni][0] * inv0, oacc[ni][1] * inv0));
        *reinterpret_cast<uint32_t*>(&o[ob1 + cc]) =
            pack_h2(make_float2(oacc[ni][2] * inv1, oacc[ni][3] * inv1));
    }
}

// ---------------- embedding + PE (+ pad mask), dual fp32/fp16 output ----------------
__global__ void embed_pe_kernel(const int* __restrict__ toks,
                                const float* __restrict__ emb,
                                float* __restrict__ out,
                                __half* __restrict__ outh,
                                unsigned char* __restrict__ mask) {
    int pos = blockIdx.x % Sc;
    int b   = blockIdx.x / Sc;
    int tok = toks[b * Sc + pos];
    int t = threadIdx.x;
    if (t == 0) mask[b * Sc + pos] = (tok == 0) ? 1 : 0;
    const float c = -logf(10000.0f) / (float)Dc;
    size_t base = ((size_t)b * Sc + pos) * Dc;
    #pragma unroll
    for (int d = t; d < Dc; d += 256) {
        int i = d >> 1;
        float freq = __expf((float)(2 * i) * c);
        float ang  = (float)pos * freq;
        float pe   = (d & 1) ? cosf(ang) : sinf(ang);
        float v = emb[(size_t)tok * Dc + d] + pe;
        out[base + d] = v;
        outh[base + d] = __float2half_rn(v);
    }
}

// ---------------- LayerNorm: dual fp32 + fp16 output (warp per row) ----------------
__global__ void __launch_bounds__(256) ln_kernel(const float* __restrict__ xin,
                                                 const float* __restrict__ gamma,
                                                 const float* __restrict__ beta,
                                                 float* __restrict__ out,
                                                 __half* __restrict__ outh) {
    int warp = threadIdx.x >> 5, lane = threadIdx.x & 31;
    size_t row = (size_t)blockIdx.x * 8 + warp;
    size_t base = row * Dc;
    float4 v[4];
    float sum = 0.f;
    #pragma unroll
    for (int i = 0; i < 4; ++i) {
        v[i] = *reinterpret_cast<const float4*>(&xin[base + lane * 4 + i * 128]);
        sum += v[i].x + v[i].y + v[i].z + v[i].w;
    }
    #pragma unroll
    for (int s = 16; s > 0; s >>= 1) sum += __shfl_xor_sync(0xffffffffu, sum, s);
    float mu = sum * (1.0f / Dc);
    float var = 0.f;
    #pragma unroll
    for (int i = 0; i < 4; ++i) {
        v[i].x -= mu; v[i].y -= mu; v[i].z -= mu; v[i].w -= mu;
        var += v[i].x * v[i].x + v[i].y * v[i].y + v[i].z * v[i].z + v[i].w * v[i].w;
    }
    #pragma unroll
    for (int s = 16; s > 0; s >>= 1) var += __shfl_xor_sync(0xffffffffu, var, s);
    float inv = rsqrtf(var * (1.0f / Dc) + EPSc);
    #pragma unroll
    for (int i = 0; i < 4; ++i) {
        int col = lane * 4 + i * 128;
        float4 gv = *reinterpret_cast<const float4*>(&gamma[col]);
        float4 bv = *reinterpret_cast<const float4*>(&beta[col]);
        float4 o;
        o.x = v[i].x * inv * gv.x + bv.x;
        o.y = v[i].y * inv * gv.y + bv.y;
        o.z = v[i].z * inv * gv.z + bv.z;
        o.w = v[i].w * inv * gv.w + bv.w;
        *reinterpret_cast<float4*>(&out[base + col]) = o;
        uint2 hw = make_uint2(pack_h2(make_float2(o.x, o.y)),
                              pack_h2(make_float2(o.z, o.w)));
        *reinterpret_cast<uint2*>(&outh[base + col]) = hw;
    }
}

// ---------------- host orchestration ----------------
// N=512 GEMMs use the M-tile-64 kernel (256 CTAs, fills the chip).
static void launch_gemm_f(const __half* A, const __half* BT, const float* bias,
                          const float* resid, float* C, int M, int N, int K) {
    dim3 grid(N / 128, M / 64);
    gemm_mma64<false, false><<<grid, 128, GEMM_SMEM64>>>(A, BT, bias, resid, C, M, N, K);
}
static void launch_gemm_h64(const __half* A, const __half* BT, const float* bias,
                            __half* C, int M, int N, int K) {
    dim3 grid(N / 128, M / 64);
    gemm_mma64<false, true><<<grid, 128, GEMM_SMEM64>>>(A, BT, bias, nullptr, C, M, N, K);
}
static void launch_gemm_h(const __half* A, const __half* BT, const float* bias,
                          __half* C, int M, int N, int K, bool relu) {
    dim3 grid(N / 128, M / 128);
    if (relu) gemm_mma<true,  true><<<grid, 256, GEMM_SMEM>>>(A, BT, bias, nullptr, C, M, N, K);
    else      gemm_mma<false, true><<<grid, 256, GEMM_SMEM>>>(A, BT, bias, nullptr, C, M, N, K);
}

extern "C" void kernel_launch(void* const* d_in, const int* in_sizes, int n_in,
                              void* d_out, int out_size) {
    const int*   inputs  = (const int*)d_in[0];
    const int*   outputs = (const int*)d_in[1];
    const float* emi = (const float*)d_in[2];
    const float* emo = (const float*)d_in[3];
    const float* enc_attn_w = (const float*)d_in[4];
    const float* enc_attn_b = (const float*)d_in[5];
    const float* enc_ln     = (const float*)d_in[6];
    const float* enc_ffn_w1 = (const float*)d_in[7];
    const float* enc_ffn_b1 = (const float*)d_in[8];
    const float* enc_ffn_w2 = (const float*)d_in[9];
    const float* enc_ffn_b2 = (const float*)d_in[10];
    const float* dec_self_w  = (const float*)d_in[11];
    const float* dec_self_b  = (const float*)d_in[12];
    const float* dec_cross_w = (const float*)d_in[13];
    const float* dec_cross_b = (const float*)d_in[14];
    const float* dec_ln      = (const float*)d_in[15];
    const float* dec_ffn_w1 = (const float*)d_in[16];
    const float* dec_ffn_b1 = (const float*)d_in[17];
    const float* dec_ffn_w2 = (const float*)d_in[18];
    const float* dec_ffn_b2 = (const float*)d_in[19];

    float *xp, *yp, *tmpp;
    __half *xh, *yh, *qkvh, *qh, *attnh, *hidh, *kvh;
    __half *wta_enc, *wta_self, *wta_cross, *wt_ef1, *wt_ef2, *wt_df1, *wt_df2;
    unsigned char *mxp, *myp;
    cudaGetSymbolAddress((void**)&xp, g_x);
    cudaGetSymbolAddress((void**)&yp, g_y);
    cudaGetSymbolAddress((void**)&tmpp, g_tmp);
    cudaGetSymbolAddress((void**)&xh, g_xh);
    cudaGetSymbolAddress((void**)&yh, g_yh);
    cudaGetSymbolAddress((void**)&qkvh, g_qkvh);
    cudaGetSymbolAddress((void**)&qh, g_qh);
    cudaGetSymbolAddress((void**)&attnh, g_attnh);
    cudaGetSymbolAddress((void**)&hidh, g_hidh);
    cudaGetSymbolAddress((void**)&kvh, g_kvh);
    cudaGetSymbolAddress((void**)&mxp, g_mx);
    cudaGetSymbolAddress((void**)&myp, g_my);
    cudaGetSymbolAddress((void**)&wta_enc,   g_wt_enc_attn);
    cudaGetSymbolAddress((void**)&wta_self,  g_wt_dec_self);
    cudaGetSymbolAddress((void**)&wta_cross, g_wt_dec_cross);
    cudaGetSymbolAddress((void**)&wt_ef1, g_wt_enc_f1);
    cudaGetSymbolAddress((void**)&wt_ef2, g_wt_enc_f2);
    cudaGetSymbolAddress((void**)&wt_df1, g_wt_dec_f1);
    cudaGetSymbolAddress((void**)&wt_df2, g_wt_dec_f2);

    cudaFuncSetAttribute(flash_attn, cudaFuncAttributeMaxDynamicSharedMemorySize, FLASH_SMEM);
    cudaFuncSetAttribute(gemm_mma<false, true >, cudaFuncAttributeMaxDynamicSharedMemorySize, GEMM_SMEM);
    cudaFuncSetAttribute(gemm_mma<true,  true >, cudaFuncAttributeMaxDynamicSharedMemorySize, GEMM_SMEM);
    cudaFuncSetAttribute(gemm_mma64<false, false>, cudaFuncAttributeMaxDynamicSharedMemorySize, GEMM_SMEM64);
    cudaFuncSetAttribute(gemm_mma64<false, true >, cudaFuncAttributeMaxDynamicSharedMemorySize, GEMM_SMEM64);
    cudaFuncSetAttribute(gemm_kv_all, cudaFuncAttributeMaxDynamicSharedMemorySize, GEMM_SMEM);

    // -------- weight transposes (fp32 -> fp16, [N][K]) --------
    dim3 tblk(32, 8);
    transpose_h<<<dim3(Dc / 32, Dc / 32, Lc * 4), tblk>>>(enc_attn_w,  wta_enc,   Dc, Dc);
    transpose_h<<<dim3(Dc / 32, Dc / 32, Lc * 4), tblk>>>(dec_self_w,  wta_self,  Dc, Dc);
    transpose_h<<<dim3(Dc / 32, Dc / 32, Lc * 4), tblk>>>(dec_cross_w, wta_cross, Dc, Dc);
    transpose_h<<<dim3(HIDc / 32, Dc / 32, Lc), tblk>>>(enc_ffn_w1, wt_ef1, Dc, HIDc);
    transpose_h<<<dim3(Dc / 32, HIDc / 32, Lc), tblk>>>(enc_ffn_w2, wt_ef2, HIDc, Dc);
    transpose_h<<<dim3(HIDc / 32, Dc / 32, Lc), tblk>>>(dec_ffn_w1, wt_df1, Dc, HIDc);
    transpose_h<<<dim3(Dc / 32, HIDc / 32, Lc), tblk>>>(dec_ffn_w2, wt_df2, HIDc, Dc);

    dim3 blk(256);
    embed_pe_kernel<<<BSc, blk>>>(inputs,  emi, xp, xh, mxp);
    embed_pe_kernel<<<BSc, blk>>>(outputs, emo, yp, yh, myp);

    int lng = BSc / 8;
    dim3 gfl(Sc / 64, Bc * NHc);

    // ---------------- encoder ----------------
    for (int l = 0; l < Lc; ++l) {
        const __half* wT = wta_enc + (size_t)l * 4 * Dc * Dc;
        const float* ab = enc_attn_b + (size_t)l * 4 * Dc;
        launch_gemm_h(xh, wT, ab, qkvh, BSc, 3 * Dc, Dc, false);
        flash_attn<<<gfl, 128, FLASH_SMEM>>>(qkvh, 3 * Dc, qkvh + Dc, qkvh + 2 * Dc, 3 * Dc,
                                             mxp, mxp, attnh, 0);
        launch_gemm_f(attnh, wT + 3 * (size_t)Dc * Dc, ab + 3 * Dc, xp, tmpp, BSc, Dc, Dc);
        const float* ln0 = enc_ln + (((size_t)l * 2 + 0) * 2) * Dc;
        ln_kernel<<<lng, blk>>>(tmpp, ln0, ln0 + Dc, xp, xh);
        launch_gemm_h(xh, wt_ef1 + (size_t)l * Dc * HIDc, enc_ffn_b1 + (size_t)l * HIDc,
                      hidh, BSc, HIDc, Dc, true);
        launch_gemm_f(hidh, wt_ef2 + (size_t)l * Dc * HIDc, enc_ffn_b2 + (size_t)l * Dc,
                      xp, tmpp, BSc, Dc, HIDc);
        const float* ln1 = enc_ln + (((size_t)l * 2 + 1) * 2) * Dc;
        ln_kernel<<<lng, blk>>>(tmpp, ln1, ln1 + Dc, xp, xh);
    }

    // -------- all-layer cross KV projections, one batched launch --------
    {
        dim3 gkv(2 * Dc / 128, BSc / 128, Lc);
        gemm_kv_all<<<gkv, 256, GEMM_SMEM>>>(xh, wta_cross, dec_cross_b, kvh);
    }

    // ---------------- decoder ----------------
    float* fout = (float*)d_out;
    for (int l = 0; l < Lc; ++l) {
        const __half* swT = wta_self + (size_t)l * 4 * Dc * Dc;
        const float* sb  = dec_self_b + (size_t)l * 4 * Dc;
        launch_gemm_h(yh, swT, sb, qkvh, BSc, 3 * Dc, Dc, false);
        flash_attn<<<gfl, 128, FLASH_SMEM>>>(qkvh, 3 * Dc, qkvh + Dc, qkvh + 2 * Dc, 3 * Dc,
                                             myp, myp, attnh, 1);
        launch_gemm_f(attnh, swT + 3 * (size_t)Dc * Dc, sb + 3 * Dc, yp, tmpp, BSc, Dc, Dc);
        const float* ln0 = dec_ln + (((size_t)l * 3 + 0) * 2) * Dc;
        ln_kernel<<<lng, blk>>>(tmpp, ln0, ln0 + Dc, yp, yh);

        const __half* cwT = wta_cross + (size_t)l * 4 * Dc * Dc;
        const float* cb  = dec_cross_b + (size_t)l * 4 * Dc;
        __half* kv = kvh + (size_t)l * BSc * 2 * Dc;
        launch_gemm_h64(yh, cwT, cb, qh, BSc, Dc, Dc);
        flash_attn<<<gfl, 128, FLASH_SMEM>>>(qh, Dc, kv, kv + Dc, 2 * Dc,
                                             myp, mxp, attnh, 0);
        launch_gemm_f(attnh, cwT + 3 * (size_t)Dc * Dc, cb + 3 * Dc, yp, tmpp, BSc, Dc, Dc);
        const float* ln1 = dec_ln + (((size_t)l * 3 + 1) * 2) * Dc;
        ln_kernel<<<lng, blk>>>(tmpp, ln1, ln1 + Dc, yp, yh);

        launch_gemm_h(yh, wt_df1 + (size_t)l * Dc * HIDc, dec_ffn_b1 + (size_t)l * HIDc,
                      hidh, BSc, HIDc, Dc, true);
        launch_gemm_f(hidh, wt_df2 + (size_t)l * Dc * HIDc, dec_ffn_b2 + (size_t)l * Dc,
                      yp, tmpp, BSc, Dc, HIDc);
        const float* ln2 = dec_ln + (((size_t)l * 3 + 2) * 2) * Dc;
        float* dst = (l == Lc - 1) ? fout : yp;
        ln_kernel<<<lng, blk>>>(tmpp, ln2, ln2 + Dc, dst, yh);
    }
    (void)in_sizes; (void)n_in; (void)out_size;
}

// round 16
// speedup vs baseline: 1.5633x; 1.5633x over previous
#include <cuda_runtime.h>
#include <cuda_fp16.h>
#include <math.h>
#include <cstdint>

// ---------------- problem constants ----------------
#define Bc   8
#define Sc   512
#define Dc   512
#define NHc  8
#define DHc  64
#define Lc   6
#define HIDc 2048
#define EPSc 1e-5f
#define BSc  (Bc * Sc)          // 4096 tokens
#define SCALEc 0.125f           // 1/sqrt(64)

// ---------------- device scratch ----------------
__device__ float  g_x[BSc * Dc];
__device__ float  g_y[BSc * Dc];
__device__ float  g_tmp[BSc * Dc];
__device__ __half g_xh[BSc * Dc];
__device__ __half g_yh[BSc * Dc];
__device__ __half g_qkvh[BSc * 3 * Dc];
__device__ __half g_qh[BSc * Dc];
__device__ __half g_attnh[BSc * Dc];
__device__ __half g_hidh[BSc * HIDc];
__device__ __half g_kvh[(size_t)Lc * BSc * 2 * Dc];   // all-layer cross KV cache
__device__ unsigned char g_mx[BSc];
__device__ unsigned char g_my[BSc];
// transposed fp16 weights: [N][K]
__device__ __half g_wt_enc_attn[Lc * 4 * Dc * Dc];
__device__ __half g_wt_dec_self[Lc * 4 * Dc * Dc];
__device__ __half g_wt_dec_cross[Lc * 4 * Dc * Dc];
__device__ __half g_wt_enc_f1[Lc * Dc * HIDc];
__device__ __half g_wt_enc_f2[Lc * Dc * HIDc];
__device__ __half g_wt_dec_f1[Lc * Dc * HIDc];
__device__ __half g_wt_dec_f2[Lc * Dc * HIDc];

__device__ __forceinline__ float neg_inf_f() { return __int_as_float(0xff800000u); }

__device__ __forceinline__ uint32_t smem_u32(const void* p) {
    uint32_t a;
    asm("{ .reg .u64 t; cvta.to.shared.u64 t, %1; cvt.u32.u64 %0, t; }" : "=r"(a) : "l"(p));
    return a;
}
__device__ __forceinline__ uint32_t pack_h2(float2 f) {
    __half2 h = __floats2half2_rn(f.x, f.y);
    return *reinterpret_cast<uint32_t*>(&h);
}

__device__ __forceinline__ void mma_16n8k16_f16(float c[4], const uint32_t a[4], const uint32_t b[2]) {
    asm volatile(
        "mma.sync.aligned.m16n8k16.row.col.f32.f16.f16.f32 "
        "{%0,%1,%2,%3}, {%4,%5,%6,%7}, {%8,%9}, {%0,%1,%2,%3};"
        : "+f"(c[0]), "+f"(c[1]), "+f"(c[2]), "+f"(c[3])
        : "r"(a[0]), "r"(a[1]), "r"(a[2]), "r"(a[3]), "r"(b[0]), "r"(b[1]));
}
#define LDSM4(r0, r1, r2, r3, addr) \
    asm volatile("ldmatrix.sync.aligned.m8n8.x4.shared.b16 {%0,%1,%2,%3}, [%4];" \
        : "=r"(r0), "=r"(r1), "=r"(r2), "=r"(r3) : "r"(addr))
#define LDSM4T(r0, r1, r2, r3, addr) \
    asm volatile("ldmatrix.sync.aligned.m8n8.x4.trans.shared.b16 {%0,%1,%2,%3}, [%4];" \
        : "=r"(r0), "=r"(r1), "=r"(r2), "=r"(r3) : "r"(addr))

// ---------------- weight transpose (fp32 -> fp16) ----------------
__global__ void transpose_h(const float* __restrict__ in, __half* __restrict__ out,
                            int R, int C) {
    __shared__ float tile[32][33];
    const float* src = in + (size_t)blockIdx.z * R * C;
    __half* dst = out + (size_t)blockIdx.z * R * C;
    int c0 = blockIdx.x * 32, r0 = blockIdx.y * 32;
    int tx = threadIdx.x, ty = threadIdx.y;
    #pragma unroll
    for (int i = 0; i < 32; i += 8)
        tile[ty + i][tx] = src[(size_t)(r0 + ty + i) * C + c0 + tx];
    __syncthreads();
    #pragma unroll
    for (int i = 0; i < 32; i += 8)
        dst[(size_t)(c0 + ty + i) * R + r0 + tx] = __float2half_rn(tile[tx][ty + i]);
}

// ---------------- fp16 mma GEMM, K-chunk 64, 3-stage cp.async ring ----------------
#define GPAD 36
#define TBUF (128 * GPAD)
#define STG_B32 (2 * TBUF)
#define STAGES 3
#define GEMM_SMEM (STAGES * STG_B32 * 4) // 110592 B -> 2 CTAs/SM

template<bool RELU, bool HALFOUT>
__device__ __forceinline__ void gemm_body(const __half* A, const __half* BT,
                                          const float* bias, const float* resid,
                                          void* Cout, int row0, int col0, int N, int K,
                                          uint32_t* gs, uint32_t sbase) {
    int tid = threadIdx.x;
    int lane = tid & 31, wid = tid >> 5;
    int wm = wid & 1, wn = wid >> 1;
    int g = lane >> 2, tg = lane & 3;
    int lrow = lane & 7, lj = lane >> 3;

    uint32_t a_off[4];
    #pragma unroll
    for (int mi = 0; mi < 4; mi++)
        a_off[mi] = (uint32_t)(((wm * 64 + mi * 16 + (lj & 1) * 8 + lrow) * GPAD
                                + (lj >> 1) * 4) * 4);
    uint32_t b_off[2];
    #pragma unroll
    for (int pr = 0; pr < 2; pr++)
        b_off[pr] = (uint32_t)(TBUF * 4
                    + ((wn * 32 + pr * 16 + (lane >> 4) * 8 + lrow) * GPAD
                       + ((lane >> 3) & 1) * 4) * 4);

    float acc[4][4][4];
    #pragma unroll
    for (int mi = 0; mi < 4; mi++)
        #pragma unroll
        for (int ni = 0; ni < 4; ni++)
            #pragma unroll
            for (int r = 0; r < 4; r++) acc[mi][ni][r] = 0.0f;

    int nch = K >> 6;

    {
        uint32_t ab = sbase, bb = sbase + TBUF * 4;
        #pragma unroll
        for (int i = 0; i < 4; ++i) {
            int idx = tid + i * 256;
            int n = idx >> 3, ch = idx & 7;
            const __half* pa = &A[(size_t)(row0 + n) * K + ch * 8];
            asm volatile("cp.async.cg.shared.global [%0], [%1], 16;"
                         :: "r"(ab + (uint32_t)(n * GPAD + ch * 4) * 4), "l"(pa));
            const __half* pb = &BT[(size_t)(col0 + n) * K + ch * 8];
            asm volatile("cp.async.cg.shared.global [%0], [%1], 16;"
                         :: "r"(bb + (uint32_t)(n * GPAD + ch * 4) * 4), "l"(pb));
        }
        asm volatile("cp.async.commit_group;" ::: "memory");
    }

    for (int c = 0; c < nch; ++c) {
        if (c + 1 < nch) {
            int k0 = (c + 1) << 6;
            uint32_t stoff = (uint32_t)(((c + 1) % STAGES) * STG_B32) * 4;
            uint32_t ab = sbase + stoff, bb = ab + TBUF * 4;
            #pragma unroll
            for (int i = 0; i < 4; ++i) {
                int idx = tid + i * 256;
                int n = idx >> 3, ch = idx & 7;
                const __half* pa = &A[(size_t)(row0 + n) * K + k0 + ch * 8];
                asm volatile("cp.async.cg.shared.global [%0], [%1], 16;"
                             :: "r"(ab + (uint32_t)(n * GPAD + ch * 4) * 4), "l"(pa));
                const __half* pb = &BT[(size_t)(col0 + n) * K + k0 + ch * 8];
                asm volatile("cp.async.cg.shared.global [%0], [%1], 16;"
                             :: "r"(bb + (uint32_t)(n * GPAD + ch * 4) * 4), "l"(pb));
            }
        }
        asm volatile("cp.async.commit_group;" ::: "memory");
        asm volatile("cp.async.wait_group 1;" ::: "memory");
        __syncthreads();

        uint32_t stb = sbase + (uint32_t)((c % STAGES) * STG_B32) * 4;

        #pragma unroll
        for (int ki = 0; ki < 4; ++ki) {
            uint32_t ko = (uint32_t)ki * 32;
            uint32_t afr[4][4];
            #pragma unroll
            for (int mi = 0; mi < 4; mi++)
                LDSM4(afr[mi][0], afr[mi][1], afr[mi][2], afr[mi][3], stb + a_off[mi] + ko);
            uint32_t bfr[4][2];
            {
                uint32_t t0, t1, t2, t3;
                LDSM4(t0, t1, t2, t3, stb + b_off[0] + ko);
                bfr[0][0] = t0; bfr[0][1] = t1; bfr[1][0] = t2; bfr[1][1] = t3;
                LDSM4(t0, t1, t2, t3, stb + b_off[1] + ko);
                bfr[2][0] = t0; bfr[2][1] = t1; bfr[3][0] = t2; bfr[3][1] = t3;
            }
            #pragma unroll
            for (int mi = 0; mi < 4; mi++)
                #pragma unroll
                for (int ni = 0; ni < 4; ni++)
                    mma_16n8k16_f16(acc[mi][ni], afr[mi], bfr[ni]);
        }
    }

    #pragma unroll
    for (int mi = 0; mi < 4; mi++) {
        int r0r = row0 + wm * 64 + mi * 16 + g;
        #pragma unroll
        for (int ni = 0; ni < 4; ni++) {
            int cb = col0 + wn * 32 + ni * 8 + tg * 2;
            float b0 = bias[cb], b1 = bias[cb + 1];
            float v0 = acc[mi][ni][0] + b0, v1 = acc[mi][ni][1] + b1;
            float v2 = acc[mi][ni][2] + b0, v3 = acc[mi][ni][3] + b1;
            if (resid) {
                float2 r0v = *reinterpret_cast<const float2*>(&resid[(size_t)(r0r)     * N + cb]);
                float2 r1v = *reinterpret_cast<const float2*>(&resid[(size_t)(r0r + 8) * N + cb]);
                v0 += r0v.x; v1 += r0v.y; v2 += r1v.x; v3 += r1v.y;
            }
            if (RELU) { v0 = fmaxf(v0, 0.f); v1 = fmaxf(v1, 0.f);
                        v2 = fmaxf(v2, 0.f); v3 = fmaxf(v3, 0.f); }
            if (HALFOUT) {
                __half* Ch = (__half*)Cout;
                *reinterpret_cast<uint32_t*>(&Ch[(size_t)(r0r)     * N + cb]) = pack_h2(make_float2(v0, v1));
                *reinterpret_cast<uint32_t*>(&Ch[(size_t)(r0r + 8) * N + cb]) = pack_h2(make_float2(v2, v3));
            } else {
                float* Cf = (float*)Cout;
                *reinterpret_cast<float2*>(&Cf[(size_t)(r0r)     * N + cb]) = make_float2(v0, v1);
                *reinterpret_cast<float2*>(&Cf[(size_t)(r0r + 8) * N + cb]) = make_float2(v2, v3);
            }
        }
    }
}

template<bool RELU, bool HALFOUT>
__global__ void __launch_bounds__(256) gemm_mma(const __half* __restrict__ A,
                                                const __half* __restrict__ BT,
                                                const float* __restrict__ bias,
                                                const float* __restrict__ resid,
                                                void* __restrict__ Cout,
                                                int M, int N, int K) {
    extern __shared__ uint32_t gs[];
    gemm_body<RELU, HALFOUT>(A, BT, bias, resid, Cout,
                             blockIdx.y * 128, blockIdx.x * 128, N, K, gs, smem_u32(gs));
}

// batched cross-attn KV projection for ALL layers: z = layer.
__global__ void __launch_bounds__(256) gemm_kv_all(const __half* __restrict__ A,
                                                   const __half* __restrict__ wbase,
                                                   const float* __restrict__ bbase,
                                                   __half* __restrict__ Cbase) {
    extern __shared__ uint32_t gs[];
    int l = blockIdx.z;
    const __half* BT = wbase + (size_t)l * 4 * Dc * Dc + (size_t)Dc * Dc;
    const float* bias = bbase + (size_t)l * 4 * Dc + Dc;
    __half* C = Cbase + (size_t)l * BSc * 2 * Dc;
    gemm_body<false, true>(A, BT, bias, nullptr, C,
                           blockIdx.y * 128, blockIdx.x * 128, 2 * Dc, Dc, gs, smem_u32(gs));
}

// ---------------- flash attention: q-tile 64, 128 threads, cp.async K/V ring ----------------
// smem layout (words): Q[64*FW] | K0[64*FW] | V0[64*FW] | K1[64*FW] | V1[64*FW] | masks[2][64]
#define FW 36
#define FLASH_SMEM (320 * FW * 4 + 128)

__global__ void __launch_bounds__(128) flash_attn(
    const __half* __restrict__ q, int ldq,
    const __half* __restrict__ k, const __half* __restrict__ v, int ldkv,
    const unsigned char* __restrict__ mqg, const unsigned char* __restrict__ mkg,
    __half* __restrict__ o, int causal)
{
    extern __shared__ char sm[];
    uint32_t smb = smem_u32(sm);
    unsigned char* mks = reinterpret_cast<unsigned char*>(sm) + 320 * FW * 4;

    int tid = threadIdx.x, lane = tid & 31, wid = tid >> 5;
    int bh = blockIdx.y, b = bh >> 3, h = bh & 7;
    int qt = causal ? ((int)gridDim.x - 1 - (int)blockIdx.x) : (int)blockIdx.x;
    int q0 = qt * 64;
    const __half* Qg = q + (size_t)b * Sc * ldq + h * DHc;
    const __half* Kg = k + (size_t)b * Sc * ldkv + h * DHc;
    const __half* Vg = v + (size_t)b * Sc * ldkv + h * DHc;
    int g = lane >> 2, tg = lane & 3;
    int lrow = lane & 7, lj = lane >> 3;
    int rg = wid * 16 + g;
    int qi0 = q0 + rg, qi1 = qi0 + 8;

    // per-thread load geometry (64 rows x 8 16B-chunks / 128 threads = 4 passes)
    int lr = tid >> 3, lc8 = tid & 7;

    // fragment offsets (bytes). kbase/vbase select buffer.
    uint32_t q_off = (uint32_t)(((wid * 16 + (lj & 1) * 8 + lrow) * FW + (lj >> 1) * 4) * 4);
    uint32_t k_rel[4], v_rel[4];
    #pragma unroll
    for (int pr = 0; pr < 4; pr++) {
        k_rel[pr] = (uint32_t)(((pr * 16 + (lane >> 4) * 8 + lrow) * FW
                                + ((lane >> 3) & 1) * 4) * 4);
        v_rel[pr] = (uint32_t)(((((lane >> 3) & 1) * 8 + lrow) * FW
                                + (2 * pr + (lane >> 4)) * 4) * 4);
    }

    // ---- prologue: Q + tile 0 via cp.async ----
    #pragma unroll
    for (int i = 0; i < 4; ++i) {
        int r = lr + i * 16;
        const __half* pq = &Qg[(size_t)(q0 + r) * ldq + lc8 * 8];
        asm volatile("cp.async.cg.shared.global [%0], [%1], 16;"
                     :: "r"(smb + (uint32_t)((r * FW + lc8 * 4) * 4)), "l"(pq));
    }
    {
        uint32_t kb = smb + (uint32_t)(64 * FW * 4);
        uint32_t vb = smb + (uint32_t)(128 * FW * 4);
        #pragma unroll
        for (int i = 0; i < 4; ++i) {
            int r = lr + i * 16;
            uint32_t off = (uint32_t)((r * FW + lc8 * 4) * 4);
            const __half* pk = &Kg[(size_t)r * ldkv + lc8 * 8];
            asm volatile("cp.async.cg.shared.global [%0], [%1], 16;" :: "r"(kb + off), "l"(pk));
            const __half* pv = &Vg[(size_t)r * ldkv + lc8 * 8];
            asm volatile("cp.async.cg.shared.global [%0], [%1], 16;" :: "r"(vb + off), "l"(pv));
        }
        asm volatile("cp.async.commit_group;" ::: "memory");
    }
    if (tid < 64) mks[tid] = mkg[b * Sc + tid];
    bool mrow0 = mqg[b * Sc + qi0] != 0;
    bool mrow1 = mqg[b * Sc + qi1] != 0;

    float m0 = -1e30f, m1 = -1e30f, l0 = 0.f, l1 = 0.f;
    float oacc[8][4];
    #pragma unroll
    for (int ni = 0; ni < 8; ni++) { oacc[ni][0] = oacc[ni][1] = oacc[ni][2] = oacc[ni][3] = 0.f; }

    int nkt = causal ? ((q0 >> 6) + 1) : (Sc / 64);
    for (int kt = 0; kt < nkt; ++kt) {
        int buf = kt & 1;
        asm volatile("cp.async.wait_group 0;" ::: "memory");   // tile kt (and Q on kt=0) landed
        __syncthreads();                                        // all readers of buf^1 done too

        // prefetch tile kt+1 into buf^1 (overlaps with compute below)
        if (kt + 1 < nkt) {
            int k0n = (kt + 1) * 64;
            uint32_t kb = smb + (uint32_t)((64 + 128 * (buf ^ 1)) * FW * 4);
            uint32_t vb = smb + (uint32_t)((128 + 128 * (buf ^ 1)) * FW * 4);
            #pragma unroll
            for (int i = 0; i < 4; ++i) {
                int r = lr + i * 16;
                uint32_t off = (uint32_t)((r * FW + lc8 * 4) * 4);
                const __half* pk = &Kg[(size_t)(k0n + r) * ldkv + lc8 * 8];
                asm volatile("cp.async.cg.shared.global [%0], [%1], 16;" :: "r"(kb + off), "l"(pk));
                const __half* pv = &Vg[(size_t)(k0n + r) * ldkv + lc8 * 8];
                asm volatile("cp.async.cg.shared.global [%0], [%1], 16;" :: "r"(vb + off), "l"(pv));
            }
            asm volatile("cp.async.commit_group;" ::: "memory");
            if (tid < 64) mks[(buf ^ 1) * 64 + tid] = mkg[b * Sc + k0n + tid];
        }

        int k0 = kt * 64;
        uint32_t kbase = smb + (uint32_t)((64 + 128 * buf) * FW * 4);
        uint32_t vbase = smb + (uint32_t)((128 + 128 * buf) * FW * 4);
        const unsigned char* mk_t = mks + buf * 64;

        // ---- S = Q @ K^T ----
        float s[8][4];
        #pragma unroll
        for (int ni = 0; ni < 8; ni++) { s[ni][0] = s[ni][1] = s[ni][2] = s[ni][3] = 0.f; }
        #pragma unroll
        for (int ki = 0; ki < 4; ++ki) {
            uint32_t ko = (uint32_t)ki * 32;
            uint32_t a[4];
            LDSM4(a[0], a[1], a[2], a[3], smb + q_off + ko);
            uint32_t bfr[8][2];
            #pragma unroll
            for (int pr = 0; pr < 4; pr++) {
                uint32_t t0, t1, t2, t3;
                LDSM4(t0, t1, t2, t3, kbase + k_rel[pr] + ko);
                bfr[2 * pr][0] = t0; bfr[2 * pr][1] = t1;
                bfr[2 * pr + 1][0] = t2; bfr[2 * pr + 1][1] = t3;
            }
            #pragma unroll
            for (int ni = 0; ni < 8; ni++)
                mma_16n8k16_f16(s[ni], a, bfr[ni]);
        }

        // ---- scale + mask + online softmax (P in registers) ----
        float rmax0 = neg_inf_f(), rmax1 = neg_inf_f();
        #pragma unroll
        for (int ni = 0; ni < 8; ni++) {
            int cloc = ni * 8 + 2 * tg;
            int cg = k0 + cloc;
            bool mkA = mk_t[cloc] != 0, mkB = mk_t[cloc + 1] != 0;
            float v0 = (mrow0 || mkA || (causal && cg     > qi0)) ? neg_inf_f() : s[ni][0] * SCALEc;
            float v1 = (mrow0 || mkB || (causal && cg + 1 > qi0)) ? neg_inf_f() : s[ni][1] * SCALEc;
            float v2 = (mrow1 || mkA || (causal && cg     > qi1)) ? neg_inf_f() : s[ni][2] * SCALEc;
            float v3 = (mrow1 || mkB || (causal && cg + 1 > qi1)) ? neg_inf_f() : s[ni][3] * SCALEc;
            s[ni][0] = v0; s[ni][1] = v1; s[ni][2] = v2; s[ni][3] = v3;
            rmax0 = fmaxf(rmax0, fmaxf(v0, v1));
            rmax1 = fmaxf(rmax1, fmaxf(v2, v3));
        }
        rmax0 = fmaxf(rmax0, __shfl_xor_sync(0xffffffffu, rmax0, 1));
        rmax0 = fmaxf(rmax0, __shfl_xor_sync(0xffffffffu, rmax0, 2));
        rmax1 = fmaxf(rmax1, __shfl_xor_sync(0xffffffffu, rmax1, 1));
        rmax1 = fmaxf(rmax1, __shfl_xor_sync(0xffffffffu, rmax1, 2));

        float mn0 = fmaxf(m0, rmax0), mn1 = fmaxf(m1, rmax1);
        float sc0 = __expf(m0 - mn0), sc1 = __expf(m1 - mn1);
        float rs0 = 0.f, rs1 = 0.f;
        uint32_t pp[8][2];
        #pragma unroll
        for (int ni = 0; ni < 8; ni++) {
            float p0 = __expf(s[ni][0] - mn0), p1 = __expf(s[ni][1] - mn0);
            float p2 = __expf(s[ni][2] - mn1), p3 = __expf(s[ni][3] - mn1);
            rs0 += p0 + p1; rs1 += p2 + p3;
            pp[ni][0] = pack_h2(make_float2(p0, p1));
            pp[ni][1] = pack_h2(make_float2(p2, p3));
        }
        rs0 += __shfl_xor_sync(0xffffffffu, rs0, 1);
        rs0 += __shfl_xor_sync(0xffffffffu, rs0, 2);
        rs1 += __shfl_xor_sync(0xffffffffu, rs1, 1);
        rs1 += __shfl_xor_sync(0xffffffffu, rs1, 2);
        l0 = l0 * sc0 + rs0; l1 = l1 * sc1 + rs1;
        m0 = mn0; m1 = mn1;
        #pragma unroll
        for (int ni = 0; ni < 8; ni++) {
            oacc[ni][0] *= sc0; oacc[ni][1] *= sc0;
            oacc[ni][2] *= sc1; oacc[ni][3] *= sc1;
        }

        // ---- O += P @ V ----
        #pragma unroll
        for (int ki = 0; ki < 4; ++ki) {
            uint32_t vko = (uint32_t)ki * 16 * FW * 4;
            uint32_t a[4] = { pp[2 * ki][0], pp[2 * ki][1],
                              pp[2 * ki + 1][0], pp[2 * ki + 1][1] };
            uint32_t bfr[8][2];
            #pragma unroll
            for (int pr = 0; pr < 4; pr++) {
                uint32_t t0, t1, t2, t3;
                LDSM4T(t0, t1, t2, t3, vbase + v_rel[pr] + vko);
                bfr[2 * pr][0] = t0; bfr[2 * pr][1] = t1;
                bfr[2 * pr + 1][0] = t2; bfr[2 * pr + 1][1] = t3;
            }
            #pragma unroll
            for (int ni = 0; ni < 8; ni++)
                mma_16n8k16_f16(oacc[ni], a, bfr[ni]);
        }
    }

    float inv0 = (l0 > 0.f) ? 1.f / l0 : 0.f;
    float inv1 = (l1 > 0.f) ? 1.f / l1 : 0.f;
    size_t ob0 = ((size_t)b * Sc + qi0) * Dc + h * DHc;
    size_t ob1 = ((size_t)b * Sc + qi1) * Dc + h * DHc;
    #pragma unroll
    for (int ni = 0; ni < 8; ni++) {
        int cc = ni * 8 + 2 * tg;
        *reinterpret_cast<uint32_t*>(&o[ob0 + cc]) =
            pack_h2(make_float2(oacc[ni][0] * inv0, oacc[ni][1] * inv0));
        *reinterpret_cast<uint32_t*>(&o[ob1 + cc]) =
            pack_h2(make_float2(oacc[ni][2] * inv1, oacc[ni][3] * inv1));
    }
}

// ---------------- embedding + PE (+ pad mask), dual fp32/fp16 output ----------------
__global__ void embed_pe_kernel(const int* __restrict__ toks,
                                const float* __restrict__ emb,
                                float* __restrict__ out,
                                __half* __restrict__ outh,
                                unsigned char* __restrict__ mask) {
    int pos = blockIdx.x % Sc;
    int b   = blockIdx.x / Sc;
    int tok = toks[b * Sc + pos];
    int t = threadIdx.x;
    if (t == 0) mask[b * Sc + pos] = (tok == 0) ? 1 : 0;
    const float c = -logf(10000.0f) / (float)Dc;
    size_t base = ((size_t)b * Sc + pos) * Dc;
    #pragma unroll
    for (int d = t; d < Dc; d += 256) {
        int i = d >> 1;
        float freq = __expf((float)(2 * i) * c);
        float ang  = (float)pos * freq;
        float pe   = (d & 1) ? cosf(ang) : sinf(ang);
        float v = emb[(size_t)tok * Dc + d] + pe;
        out[base + d] = v;
        outh[base + d] = __float2half_rn(v);
    }
}

// ---------------- LayerNorm: dual fp32 + fp16 output (warp per row) ----------------
__global__ void __launch_bounds__(256) ln_kernel(const float* __restrict__ xin,
                                                 const float* __restrict__ gamma,
                                                 const float* __restrict__ beta,
                                                 float* __restrict__ out,
                                                 __half* __restrict__ outh) {
    int warp = threadIdx.x >> 5, lane = threadIdx.x & 31;
    size_t row = (size_t)blockIdx.x * 8 + warp;
    size_t base = row * Dc;
    float4 v[4];
    float sum = 0.f;
    #pragma unroll
    for (int i = 0; i < 4; ++i) {
        v[i] = *reinterpret_cast<const float4*>(&xin[base + lane * 4 + i * 128]);
        sum += v[i].x + v[i].y + v[i].z + v[i].w;
    }
    #pragma unroll
    for (int s = 16; s > 0; s >>= 1) sum += __shfl_xor_sync(0xffffffffu, sum, s);
    float mu = sum * (1.0f / Dc);
    float var = 0.f;
    #pragma unroll
    for (int i = 0; i < 4; ++i) {
        v[i].x -= mu; v[i].y -= mu; v[i].z -= mu; v[i].w -= mu;
        var += v[i].x * v[i].x + v[i].y * v[i].y + v[i].z * v[i].z + v[i].w * v[i].w;
    }
    #pragma unroll
    for (int s = 16; s > 0; s >>= 1) var += __shfl_xor_sync(0xffffffffu, var, s);
    float inv = rsqrtf(var * (1.0f / Dc) + EPSc);
    #pragma unroll
    for (int i = 0; i < 4; ++i) {
        int col = lane * 4 + i * 128;
        float4 gv = *reinterpret_cast<const float4*>(&gamma[col]);
        float4 bv = *reinterpret_cast<const float4*>(&beta[col]);
        float4 o;
        o.x = v[i].x * inv * gv.x + bv.x;
        o.y = v[i].y * inv * gv.y + bv.y;
        o.z = v[i].z * inv * gv.z + bv.z;
        o.w = v[i].w * inv * gv.w + bv.w;
        *reinterpret_cast<float4*>(&out[base + col]) = o;
        uint2 hw = make_uint2(pack_h2(make_float2(o.x, o.y)),
                              pack_h2(make_float2(o.z, o.w)));
        *reinterpret_cast<uint2*>(&outh[base + col]) = hw;
    }
}

// ---------------- host orchestration ----------------
static void launch_gemm_f(const __half* A, const __half* BT, const float* bias,
                          const float* resid, float* C, int M, int N, int K) {
    dim3 grid(N / 128, M / 128);
    gemm_mma<false, false><<<grid, 256, GEMM_SMEM>>>(A, BT, bias, resid, C, M, N, K);
}
static void launch_gemm_h(const __half* A, const __half* BT, const float* bias,
                          __half* C, int M, int N, int K, bool relu) {
    dim3 grid(N / 128, M / 128);
    if (relu) gemm_mma<true,  true><<<grid, 256, GEMM_SMEM>>>(A, BT, bias, nullptr, C, M, N, K);
    else      gemm_mma<false, true><<<grid, 256, GEMM_SMEM>>>(A, BT, bias, nullptr, C, M, N, K);
}

extern "C" void kernel_launch(void* const* d_in, const int* in_sizes, int n_in,
                              void* d_out, int out_size) {
    const int*   inputs  = (const int*)d_in[0];
    const int*   outputs = (const int*)d_in[1];
    const float* emi = (const float*)d_in[2];
    const float* emo = (const float*)d_in[3];
    const float* enc_attn_w = (const float*)d_in[4];
    const float* enc_attn_b = (const float*)d_in[5];
    const float* enc_ln     = (const float*)d_in[6];
    const float* enc_ffn_w1 = (const float*)d_in[7];
    const float* enc_ffn_b1 = (const float*)d_in[8];
    const float* enc_ffn_w2 = (const float*)d_in[9];
    const float* enc_ffn_b2 = (const float*)d_in[10];
    const float* dec_self_w  = (const float*)d_in[11];
    const float* dec_self_b  = (const float*)d_in[12];
    const float* dec_cross_w = (const float*)d_in[13];
    const float* dec_cross_b = (const float*)d_in[14];
    const float* dec_ln      = (const float*)d_in[15];
    const float* dec_ffn_w1 = (const float*)d_in[16];
    const float* dec_ffn_b1 = (const float*)d_in[17];
    const float* dec_ffn_w2 = (const float*)d_in[18];
    const float* dec_ffn_b2 = (const float*)d_in[19];

    float *xp, *yp, *tmpp;
    __half *xh, *yh, *qkvh, *qh, *attnh, *hidh, *kvh;
    __half *wta_enc, *wta_self, *wta_cross, *wt_ef1, *wt_ef2, *wt_df1, *wt_df2;
    unsigned char *mxp, *myp;
    cudaGetSymbolAddress((void**)&xp, g_x);
    cudaGetSymbolAddress((void**)&yp, g_y);
    cudaGetSymbolAddress((void**)&tmpp, g_tmp);
    cudaGetSymbolAddress((void**)&xh, g_xh);
    cudaGetSymbolAddress((void**)&yh, g_yh);
    cudaGetSymbolAddress((void**)&qkvh, g_qkvh);
    cudaGetSymbolAddress((void**)&qh, g_qh);
    cudaGetSymbolAddress((void**)&attnh, g_attnh);
    cudaGetSymbolAddress((void**)&hidh, g_hidh);
    cudaGetSymbolAddress((void**)&kvh, g_kvh);
    cudaGetSymbolAddress((void**)&mxp, g_mx);
    cudaGetSymbolAddress((void**)&myp, g_my);
    cudaGetSymbolAddress((void**)&wta_enc,   g_wt_enc_attn);
    cudaGetSymbolAddress((void**)&wta_self,  g_wt_dec_self);
    cudaGetSymbolAddress((void**)&wta_cross, g_wt_dec_cross);
    cudaGetSymbolAddress((void**)&wt_ef1, g_wt_enc_f1);
    cudaGetSymbolAddress((void**)&wt_ef2, g_wt_enc_f2);
    cudaGetSymbolAddress((void**)&wt_df1, g_wt_dec_f1);
    cudaGetSymbolAddress((void**)&wt_df2, g_wt_dec_f2);

    cudaFuncSetAttribute(flash_attn, cudaFuncAttributeMaxDynamicSharedMemorySize, FLASH_SMEM);
    cudaFuncSetAttribute(gemm_mma<false, false>, cudaFuncAttributeMaxDynamicSharedMemorySize, GEMM_SMEM);
    cudaFuncSetAttribute(gemm_mma<false, true >, cudaFuncAttributeMaxDynamicSharedMemorySize, GEMM_SMEM);
    cudaFuncSetAttribute(gemm_mma<true,  true >, cudaFuncAttributeMaxDynamicSharedMemorySize, GEMM_SMEM);
    cudaFuncSetAttribute(gemm_kv_all, cudaFuncAttributeMaxDynamicSharedMemorySize, GEMM_SMEM);

    // -------- weight transposes (fp32 -> fp16, [N][K]) --------
    dim3 tblk(32, 8);
    transpose_h<<<dim3(Dc / 32, Dc / 32, Lc * 4), tblk>>>(enc_attn_w,  wta_enc,   Dc, Dc);
    transpose_h<<<dim3(Dc / 32, Dc / 32, Lc * 4), tblk>>>(dec_self_w,  wta_self,  Dc, Dc);
    transpose_h<<<dim3(Dc / 32, Dc / 32, Lc * 4), tblk>>>(dec_cross_w, wta_cross, Dc, Dc);
    transpose_h<<<dim3(HIDc / 32, Dc / 32, Lc), tblk>>>(enc_ffn_w1, wt_ef1, Dc, HIDc);
    transpose_h<<<dim3(Dc / 32, HIDc / 32, Lc), tblk>>>(enc_ffn_w2, wt_ef2, HIDc, Dc);
    transpose_h<<<dim3(HIDc / 32, Dc / 32, Lc), tblk>>>(dec_ffn_w1, wt_df1, Dc, HIDc);
    transpose_h<<<dim3(Dc / 32, HIDc / 32, Lc), tblk>>>(dec_ffn_w2, wt_df2, HIDc, Dc);

    dim3 blk(256);
    embed_pe_kernel<<<BSc, blk>>>(inputs,  emi, xp, xh, mxp);
    embed_pe_kernel<<<BSc, blk>>>(outputs, emo, yp, yh, myp);

    int lng = BSc / 8;
    dim3 gfl(Sc / 64, Bc * NHc);

    // ---------------- encoder ----------------
    for (int l = 0; l < Lc; ++l) {
        const __half* wT = wta_enc + (size_t)l * 4 * Dc * Dc;
        const float* ab = enc_attn_b + (size_t)l * 4 * Dc;
        launch_gemm_h(xh, wT, ab, qkvh, BSc, 3 * Dc, Dc, false);
        flash_attn<<<gfl, 128, FLASH_SMEM>>>(qkvh, 3 * Dc, qkvh + Dc, qkvh + 2 * Dc, 3 * Dc,
                                             mxp, mxp, attnh, 0);
        launch_gemm_f(attnh, wT + 3 * (size_t)Dc * Dc, ab + 3 * Dc, xp, tmpp, BSc, Dc, Dc);
        const float* ln0 = enc_ln + (((size_t)l * 2 + 0) * 2) * Dc;
        ln_kernel<<<lng, blk>>>(tmpp, ln0, ln0 + Dc, xp, xh);
        launch_gemm_h(xh, wt_ef1 + (size_t)l * Dc * HIDc, enc_ffn_b1 + (size_t)l * HIDc,
                      hidh, BSc, HIDc, Dc, true);
        launch_gemm_f(hidh, wt_ef2 + (size_t)l * Dc * HIDc, enc_ffn_b2 + (size_t)l * Dc,
                      xp, tmpp, BSc, Dc, HIDc);
        const float* ln1 = enc_ln + (((size_t)l * 2 + 1) * 2) * Dc;
        ln_kernel<<<lng, blk>>>(tmpp, ln1, ln1 + Dc, xp, xh);
    }

    // -------- all-layer cross KV projections, one batched launch --------
    {
        dim3 gkv(2 * Dc / 128, BSc / 128, Lc);
        gemm_kv_all<<<gkv, 256, GEMM_SMEM>>>(xh, wta_cross, dec_cross_b, kvh);
    }

    // ---------------- decoder ----------------
    float* fout = (float*)d_out;
    for (int l = 0; l < Lc; ++l) {
        const __half* swT = wta_self + (size_t)l * 4 * Dc * Dc;
        const float* sb  = dec_self_b + (size_t)l * 4 * Dc;
        launch_gemm_h(yh, swT, sb, qkvh, BSc, 3 * Dc, Dc, false);
        flash_attn<<<gfl, 128, FLASH_SMEM>>>(qkvh, 3 * Dc, qkvh + Dc, qkvh + 2 * Dc, 3 * Dc,
                                             myp, myp, attnh, 1);
        launch_gemm_f(attnh, swT + 3 * (size_t)Dc * Dc, sb + 3 * Dc, yp, tmpp, BSc, Dc, Dc);
        const float* ln0 = dec_ln + (((size_t)l * 3 + 0) * 2) * Dc;
        ln_kernel<<<lng, blk>>>(tmpp, ln0, ln0 + Dc, yp, yh);

        const __half* cwT = wta_cross + (size_t)l * 4 * Dc * Dc;
        const float* cb  = dec_cross_b + (size_t)l * 4 * Dc;
        __half* kv = kvh + (size_t)l * BSc * 2 * Dc;
        launch_gemm_h(yh, cwT, cb, qh, BSc, Dc, Dc, false);
        flash_attn<<<gfl, 128, FLASH_SMEM>>>(qh, Dc, kv, kv + Dc, 2 * Dc,
                                             myp, mxp, attnh, 0);
        launch_gemm_f(attnh, cwT + 3 * (size_t)Dc * Dc, cb + 3 * Dc, yp, tmpp, BSc, Dc, Dc);
        const float* ln1 = dec_ln + (((size_t)l * 3 + 1) * 2) * Dc;
        ln_kernel<<<lng, blk>>>(tmpp, ln1, ln1 + Dc, yp, yh);

        launch_gemm_h(yh, wt_df1 + (size_t)l * Dc * HIDc, dec_ffn_b1 + (size_t)l * HIDc,
                      hidh, BSc, HIDc, Dc, true);
        launch_gemm_f(hidh, wt_df2 + (size_t)l * Dc * HIDc, dec_ffn_b2 + (size_t)l * Dc,
                      yp, tmpp, BSc, Dc, HIDc);
        const float* ln2 = dec_ln + (((size_t)l * 3 + 2) * 2) * Dc;
        float* dst = (l == Lc - 1) ? fout : yp;
        ln_kernel<<<lng, blk>>>(tmpp, ln2, ln2 + Dc, dst, yh);
    }
    (void)in_sizes; (void)n_in; (void)out_size;
}

// round 17
// speedup vs baseline: 1.5707x; 1.0047x over previous
#include <cuda_runtime.h>
#include <cuda_fp16.h>
#include <math.h>
#include <cstdint>

// ---------------- problem constants ----------------
#define Bc   8
#define Sc   512
#define Dc   512
#define NHc  8
#define DHc  64
#define Lc   6
#define HIDc 2048
#define EPSc 1e-5f
#define BSc  (Bc * Sc)          // 4096 tokens
#define SCALEc 0.125f           // 1/sqrt(64)

// ---------------- device scratch ----------------
__device__ float  g_x[BSc * Dc];
__device__ float  g_y[BSc * Dc];
__device__ float  g_tmp[BSc * Dc];
__device__ __half g_xh[BSc * Dc];
__device__ __half g_yh[BSc * Dc];
__device__ __half g_qkvh[BSc * 3 * Dc];
__device__ __half g_qh[BSc * Dc];
__device__ __half g_attnh[BSc * Dc];
__device__ __half g_hidh[BSc * HIDc];
__device__ __half g_kvh[(size_t)Lc * BSc * 2 * Dc];   // all-layer cross KV cache
__device__ unsigned char g_mx[BSc];
__device__ unsigned char g_my[BSc];
// transposed fp16 weights: [N][K]
__device__ __half g_wt_enc_attn[Lc * 4 * Dc * Dc];
__device__ __half g_wt_dec_self[Lc * 4 * Dc * Dc];
__device__ __half g_wt_dec_cross[Lc * 4 * Dc * Dc];
__device__ __half g_wt_enc_f1[Lc * Dc * HIDc];
__device__ __half g_wt_enc_f2[Lc * Dc * HIDc];
__device__ __half g_wt_dec_f1[Lc * Dc * HIDc];
__device__ __half g_wt_dec_f2[Lc * Dc * HIDc];

__device__ __forceinline__ float neg_inf_f() { return __int_as_float(0xff800000u); }

__device__ __forceinline__ uint32_t smem_u32(const void* p) {
    uint32_t a;
    asm("{ .reg .u64 t; cvta.to.shared.u64 t, %1; cvt.u32.u64 %0, t; }" : "=r"(a) : "l"(p));
    return a;
}
__device__ __forceinline__ uint32_t pack_h2(float2 f) {
    __half2 h = __floats2half2_rn(f.x, f.y);
    return *reinterpret_cast<uint32_t*>(&h);
}

__device__ __forceinline__ void mma_16n8k16_f16(float c[4], const uint32_t a[4], const uint32_t b[2]) {
    asm volatile(
        "mma.sync.aligned.m16n8k16.row.col.f32.f16.f16.f32 "
        "{%0,%1,%2,%3}, {%4,%5,%6,%7}, {%8,%9}, {%0,%1,%2,%3};"
        : "+f"(c[0]), "+f"(c[1]), "+f"(c[2]), "+f"(c[3])
        : "r"(a[0]), "r"(a[1]), "r"(a[2]), "r"(a[3]), "r"(b[0]), "r"(b[1]));
}
#define LDSM4(r0, r1, r2, r3, addr) \
    asm volatile("ldmatrix.sync.aligned.m8n8.x4.shared.b16 {%0,%1,%2,%3}, [%4];" \
        : "=r"(r0), "=r"(r1), "=r"(r2), "=r"(r3) : "r"(addr))
#define LDSM4T(r0, r1, r2, r3, addr) \
    asm volatile("ldmatrix.sync.aligned.m8n8.x4.trans.shared.b16 {%0,%1,%2,%3}, [%4];" \
        : "=r"(r0), "=r"(r1), "=r"(r2), "=r"(r3) : "r"(addr))

// ---------------- weight transpose (fp32 -> fp16) ----------------
__global__ void transpose_h(const float* __restrict__ in, __half* __restrict__ out,
                            int R, int C) {
    __shared__ float tile[32][33];
    const float* src = in + (size_t)blockIdx.z * R * C;
    __half* dst = out + (size_t)blockIdx.z * R * C;
    int c0 = blockIdx.x * 32, r0 = blockIdx.y * 32;
    int tx = threadIdx.x, ty = threadIdx.y;
    #pragma unroll
    for (int i = 0; i < 32; i += 8)
        tile[ty + i][tx] = src[(size_t)(r0 + ty + i) * C + c0 + tx];
    __syncthreads();
    #pragma unroll
    for (int i = 0; i < 32; i += 8)
        dst[(size_t)(c0 + ty + i) * R + r0 + tx] = __float2half_rn(tile[tx][ty + i]);
}

// ---------------- fp16 mma GEMM, K-chunk 64, 3-stage cp.async ring ----------------
#define GPAD 36
#define TBUF (128 * GPAD)
#define STG_B32 (2 * TBUF)
#define STAGES 3
#define GEMM_SMEM (STAGES * STG_B32 * 4) // 110592 B -> 2 CTAs/SM

template<bool RELU, bool HALFOUT>
__device__ __forceinline__ void gemm_body(const __half* A, const __half* BT,
                                          const float* bias, const float* resid,
                                          void* Cout, int row0, int col0, int N, int K,
                                          uint32_t* gs, uint32_t sbase) {
    int tid = threadIdx.x;
    int lane = tid & 31, wid = tid >> 5;
    int wm = wid & 1, wn = wid >> 1;
    int g = lane >> 2, tg = lane & 3;
    int lrow = lane & 7, lj = lane >> 3;

    uint32_t a_off[4];
    #pragma unroll
    for (int mi = 0; mi < 4; mi++)
        a_off[mi] = (uint32_t)(((wm * 64 + mi * 16 + (lj & 1) * 8 + lrow) * GPAD
                                + (lj >> 1) * 4) * 4);
    uint32_t b_off[2];
    #pragma unroll
    for (int pr = 0; pr < 2; pr++)
        b_off[pr] = (uint32_t)(TBUF * 4
                    + ((wn * 32 + pr * 16 + (lane >> 4) * 8 + lrow) * GPAD
                       + ((lane >> 3) & 1) * 4) * 4);

    float acc[4][4][4];
    #pragma unroll
    for (int mi = 0; mi < 4; mi++)
        #pragma unroll
        for (int ni = 0; ni < 4; ni++)
            #pragma unroll
            for (int r = 0; r < 4; r++) acc[mi][ni][r] = 0.0f;

    int nch = K >> 6;

    {
        uint32_t ab = sbase, bb = sbase + TBUF * 4;
        #pragma unroll
        for (int i = 0; i < 4; ++i) {
            int idx = tid + i * 256;
            int n = idx >> 3, ch = idx & 7;
            const __half* pa = &A[(size_t)(row0 + n) * K + ch * 8];
            asm volatile("cp.async.cg.shared.global [%0], [%1], 16;"
                         :: "r"(ab + (uint32_t)(n * GPAD + ch * 4) * 4), "l"(pa));
            const __half* pb = &BT[(size_t)(col0 + n) * K + ch * 8];
            asm volatile("cp.async.cg.shared.global [%0], [%1], 16;"
                         :: "r"(bb + (uint32_t)(n * GPAD + ch * 4) * 4), "l"(pb));
        }
        asm volatile("cp.async.commit_group;" ::: "memory");
    }

    for (int c = 0; c < nch; ++c) {
        if (c + 1 < nch) {
            int k0 = (c + 1) << 6;
            uint32_t stoff = (uint32_t)(((c + 1) % STAGES) * STG_B32) * 4;
            uint32_t ab = sbase + stoff, bb = ab + TBUF * 4;
            #pragma unroll
            for (int i = 0; i < 4; ++i) {
                int idx = tid + i * 256;
                int n = idx >> 3, ch = idx & 7;
                const __half* pa = &A[(size_t)(row0 + n) * K + k0 + ch * 8];
                asm volatile("cp.async.cg.shared.global [%0], [%1], 16;"
                             :: "r"(ab + (uint32_t)(n * GPAD + ch * 4) * 4), "l"(pa));
                const __half* pb = &BT[(size_t)(col0 + n) * K + k0 + ch * 8];
                asm volatile("cp.async.cg.shared.global [%0], [%1], 16;"
                             :: "r"(bb + (uint32_t)(n * GPAD + ch * 4) * 4), "l"(pb));
            }
        }
        asm volatile("cp.async.commit_group;" ::: "memory");
        asm volatile("cp.async.wait_group 1;" ::: "memory");
        __syncthreads();

        uint32_t stb = sbase + (uint32_t)((c % STAGES) * STG_B32) * 4;

        #pragma unroll
        for (int ki = 0; ki < 4; ++ki) {
            uint32_t ko = (uint32_t)ki * 32;
            uint32_t afr[4][4];
            #pragma unroll
            for (int mi = 0; mi < 4; mi++)
                LDSM4(afr[mi][0], afr[mi][1], afr[mi][2], afr[mi][3], stb + a_off[mi] + ko);
            uint32_t bfr[4][2];
            {
                uint32_t t0, t1, t2, t3;
                LDSM4(t0, t1, t2, t3, stb + b_off[0] + ko);
                bfr[0][0] = t0; bfr[0][1] = t1; bfr[1][0] = t2; bfr[1][1] = t3;
                LDSM4(t0, t1, t2, t3, stb + b_off[1] + ko);
                bfr[2][0] = t0; bfr[2][1] = t1; bfr[3][0] = t2; bfr[3][1] = t3;
            }
            #pragma unroll
            for (int mi = 0; mi < 4; mi++)
                #pragma unroll
                for (int ni = 0; ni < 4; ni++)
                    mma_16n8k16_f16(acc[mi][ni], afr[mi], bfr[ni]);
        }
    }

    #pragma unroll
    for (int mi = 0; mi < 4; mi++) {
        int r0r = row0 + wm * 64 + mi * 16 + g;
        #pragma unroll
        for (int ni = 0; ni < 4; ni++) {
            int cb = col0 + wn * 32 + ni * 8 + tg * 2;
            float b0 = bias[cb], b1 = bias[cb + 1];
            float v0 = acc[mi][ni][0] + b0, v1 = acc[mi][ni][1] + b1;
            float v2 = acc[mi][ni][2] + b0, v3 = acc[mi][ni][3] + b1;
            if (resid) {
                float2 r0v = *reinterpret_cast<const float2*>(&resid[(size_t)(r0r)     * N + cb]);
                float2 r1v = *reinterpret_cast<const float2*>(&resid[(size_t)(r0r + 8) * N + cb]);
                v0 += r0v.x; v1 += r0v.y; v2 += r1v.x; v3 += r1v.y;
            }
            if (RELU) { v0 = fmaxf(v0, 0.f); v1 = fmaxf(v1, 0.f);
                        v2 = fmaxf(v2, 0.f); v3 = fmaxf(v3, 0.f); }
            if (HALFOUT) {
                __half* Ch = (__half*)Cout;
                *reinterpret_cast<uint32_t*>(&Ch[(size_t)(r0r)     * N + cb]) = pack_h2(make_float2(v0, v1));
                *reinterpret_cast<uint32_t*>(&Ch[(size_t)(r0r + 8) * N + cb]) = pack_h2(make_float2(v2, v3));
            } else {
                float* Cf = (float*)Cout;
                *reinterpret_cast<float2*>(&Cf[(size_t)(r0r)     * N + cb]) = make_float2(v0, v1);
                *reinterpret_cast<float2*>(&Cf[(size_t)(r0r + 8) * N + cb]) = make_float2(v2, v3);
            }
        }
    }
}

template<bool RELU, bool HALFOUT>
__global__ void __launch_bounds__(256) gemm_mma(const __half* __restrict__ A,
                                                const __half* __restrict__ BT,
                                                const float* __restrict__ bias,
                                                const float* __restrict__ resid,
                                                void* __restrict__ Cout,
                                                int M, int N, int K) {
    extern __shared__ uint32_t gs[];
    gemm_body<RELU, HALFOUT>(A, BT, bias, resid, Cout,
                             blockIdx.y * 128, blockIdx.x * 128, N, K, gs, smem_u32(gs));
}

// batched cross-attn KV projection for ALL layers: z = layer.
__global__ void __launch_bounds__(256) gemm_kv_all(const __half* __restrict__ A,
                                                   const __half* __restrict__ wbase,
                                                   const float* __restrict__ bbase,
                                                   __half* __restrict__ Cbase) {
    extern __shared__ uint32_t gs[];
    int l = blockIdx.z;
    const __half* BT = wbase + (size_t)l * 4 * Dc * Dc + (size_t)Dc * Dc;
    const float* bias = bbase + (size_t)l * 4 * Dc + Dc;
    __half* C = Cbase + (size_t)l * BSc * 2 * Dc;
    gemm_body<false, true>(A, BT, bias, nullptr, C,
                           blockIdx.y * 128, blockIdx.x * 128, 2 * Dc, Dc, gs, smem_u32(gs));
}

// ---------------- flash attention: q-tile 64, 128 threads, cp.async K/V ring ----------------
// smem layout (words): Q[64*FW] | K0[64*FW] | V0[64*FW] | K1[64*FW] | V1[64*FW] | masks[2][64]
#define FW 36
#define FLASH_SMEM (320 * FW * 4 + 128)

__global__ void __launch_bounds__(128) flash_attn(
    const __half* __restrict__ q, int ldq,
    const __half* __restrict__ k, const __half* __restrict__ v, int ldkv,
    const unsigned char* __restrict__ mqg, const unsigned char* __restrict__ mkg,
    __half* __restrict__ o, int causal)
{
    extern __shared__ char sm[];
    uint32_t smb = smem_u32(sm);
    unsigned char* mks = reinterpret_cast<unsigned char*>(sm) + 320 * FW * 4;

    int tid = threadIdx.x, lane = tid & 31, wid = tid >> 5;
    int bh = blockIdx.y, b = bh >> 3, h = bh & 7;
    int qt = causal ? ((int)gridDim.x - 1 - (int)blockIdx.x) : (int)blockIdx.x;
    int q0 = qt * 64;
    const __half* Qg = q + (size_t)b * Sc * ldq + h * DHc;
    const __half* Kg = k + (size_t)b * Sc * ldkv + h * DHc;
    const __half* Vg = v + (size_t)b * Sc * ldkv + h * DHc;
    int g = lane >> 2, tg = lane & 3;
    int lrow = lane & 7, lj = lane >> 3;
    int rg = wid * 16 + g;
    int qi0 = q0 + rg, qi1 = qi0 + 8;

    // per-thread load geometry (64 rows x 8 16B-chunks / 128 threads = 4 passes)
    int lr = tid >> 3, lc8 = tid & 7;

    // fragment offsets (bytes). kbase/vbase select buffer.
    uint32_t q_off = (uint32_t)(((wid * 16 + (lj & 1) * 8 + lrow) * FW + (lj >> 1) * 4) * 4);
    uint32_t k_rel[4], v_rel[4];
    #pragma unroll
    for (int pr = 0; pr < 4; pr++) {
        k_rel[pr] = (uint32_t)(((pr * 16 + (lane >> 4) * 8 + lrow) * FW
                                + ((lane >> 3) & 1) * 4) * 4);
        v_rel[pr] = (uint32_t)(((((lane >> 3) & 1) * 8 + lrow) * FW
                                + (2 * pr + (lane >> 4)) * 4) * 4);
    }

    // ---- prologue: Q + tile 0 via cp.async ----
    #pragma unroll
    for (int i = 0; i < 4; ++i) {
        int r = lr + i * 16;
        const __half* pq = &Qg[(size_t)(q0 + r) * ldq + lc8 * 8];
        asm volatile("cp.async.cg.shared.global [%0], [%1], 16;"
                     :: "r"(smb + (uint32_t)((r * FW + lc8 * 4) * 4)), "l"(pq));
    }
    {
        uint32_t kb = smb + (uint32_t)(64 * FW * 4);
        uint32_t vb = smb + (uint32_t)(128 * FW * 4);
        #pragma unroll
        for (int i = 0; i < 4; ++i) {
            int r = lr + i * 16;
            uint32_t off = (uint32_t)((r * FW + lc8 * 4) * 4);
            const __half* pk = &Kg[(size_t)r * ldkv + lc8 * 8];
            asm volatile("cp.async.cg.shared.global [%0], [%1], 16;" :: "r"(kb + off), "l"(pk));
            const __half* pv = &Vg[(size_t)r * ldkv + lc8 * 8];
            asm volatile("cp.async.cg.shared.global [%0], [%1], 16;" :: "r"(vb + off), "l"(pv));
        }
        asm volatile("cp.async.commit_group;" ::: "memory");
    }
    if (tid < 64) mks[tid] = mkg[b * Sc + tid];
    bool mrow0 = mqg[b * Sc + qi0] != 0;
    bool mrow1 = mqg[b * Sc + qi1] != 0;

    float m0 = -1e30f, m1 = -1e30f, l0 = 0.f, l1 = 0.f;
    float oacc[8][4];
    #pragma unroll
    for (int ni = 0; ni < 8; ni++) { oacc[ni][0] = oacc[ni][1] = oacc[ni][2] = oacc[ni][3] = 0.f; }

    int nkt = causal ? ((q0 >> 6) + 1) : (Sc / 64);
    for (int kt = 0; kt < nkt; ++kt) {
        int buf = kt & 1;
        asm volatile("cp.async.wait_group 0;" ::: "memory");   // tile kt (and Q on kt=0) landed
        __syncthreads();                                        // all readers of buf^1 done too

        // prefetch tile kt+1 into buf^1 (overlaps with compute below)
        if (kt + 1 < nkt) {
            int k0n = (kt + 1) * 64;
            uint32_t kb = smb + (uint32_t)((64 + 128 * (buf ^ 1)) * FW * 4);
            uint32_t vb = smb + (uint32_t)((128 + 128 * (buf ^ 1)) * FW * 4);
            #pragma unroll
            for (int i = 0; i < 4; ++i) {
                int r = lr + i * 16;
                uint32_t off = (uint32_t)((r * FW + lc8 * 4) * 4);
                const __half* pk = &Kg[(size_t)(k0n + r) * ldkv + lc8 * 8];
                asm volatile("cp.async.cg.shared.global [%0], [%1], 16;" :: "r"(kb + off), "l"(pk));
                const __half* pv = &Vg[(size_t)(k0n + r) * ldkv + lc8 * 8];
                asm volatile("cp.async.cg.shared.global [%0], [%1], 16;" :: "r"(vb + off), "l"(pv));
            }
            asm volatile("cp.async.commit_group;" ::: "memory");
            if (tid < 64) mks[(buf ^ 1) * 64 + tid] = mkg[b * Sc + k0n + tid];
        }

        int k0 = kt * 64;
        uint32_t kbase = smb + (uint32_t)((64 + 128 * buf) * FW * 4);
        uint32_t vbase = smb + (uint32_t)((128 + 128 * buf) * FW * 4);
        const unsigned char* mk_t = mks + buf * 64;

        // ---- S = Q @ K^T ----
        float s[8][4];
        #pragma unroll
        for (int ni = 0; ni < 8; ni++) { s[ni][0] = s[ni][1] = s[ni][2] = s[ni][3] = 0.f; }
        #pragma unroll
        for (int ki = 0; ki < 4; ++ki) {
            uint32_t ko = (uint32_t)ki * 32;
            uint32_t a[4];
            LDSM4(a[0], a[1], a[2], a[3], smb + q_off + ko);
            uint32_t bfr[8][2];
            #pragma unroll
            for (int pr = 0; pr < 4; pr++) {
                uint32_t t0, t1, t2, t3;
                LDSM4(t0, t1, t2, t3, kbase + k_rel[pr] + ko);
                bfr[2 * pr][0] = t0; bfr[2 * pr][1] = t1;
                bfr[2 * pr + 1][0] = t2; bfr[2 * pr + 1][1] = t3;
            }
            #pragma unroll
            for (int ni = 0; ni < 8; ni++)
                mma_16n8k16_f16(s[ni], a, bfr[ni]);
        }

        // ---- scale + mask + online softmax (P in registers) ----
        float rmax0 = neg_inf_f(), rmax1 = neg_inf_f();
        #pragma unroll
        for (int ni = 0; ni < 8; ni++) {
            int cloc = ni * 8 + 2 * tg;
            int cg = k0 + cloc;
            bool mkA = mk_t[cloc] != 0, mkB = mk_t[cloc + 1] != 0;
            float v0 = (mrow0 || mkA || (causal && cg     > qi0)) ? neg_inf_f() : s[ni][0] * SCALEc;
            float v1 = (mrow0 || mkB || (causal && cg + 1 > qi0)) ? neg_inf_f() : s[ni][1] * SCALEc;
            float v2 = (mrow1 || mkA || (causal && cg     > qi1)) ? neg_inf_f() : s[ni][2] * SCALEc;
            float v3 = (mrow1 || mkB || (causal && cg + 1 > qi1)) ? neg_inf_f() : s[ni][3] * SCALEc;
            s[ni][0] = v0; s[ni][1] = v1; s[ni][2] = v2; s[ni][3] = v3;
            rmax0 = fmaxf(rmax0, fmaxf(v0, v1));
            rmax1 = fmaxf(rmax1, fmaxf(v2, v3));
        }
        rmax0 = fmaxf(rmax0, __shfl_xor_sync(0xffffffffu, rmax0, 1));
        rmax0 = fmaxf(rmax0, __shfl_xor_sync(0xffffffffu, rmax0, 2));
        rmax1 = fmaxf(rmax1, __shfl_xor_sync(0xffffffffu, rmax1, 1));
        rmax1 = fmaxf(rmax1, __shfl_xor_sync(0xffffffffu, rmax1, 2));

        float mn0 = fmaxf(m0, rmax0), mn1 = fmaxf(m1, rmax1);
        float sc0 = __expf(m0 - mn0), sc1 = __expf(m1 - mn1);
        float rs0 = 0.f, rs1 = 0.f;
        uint32_t pp[8][2];
        #pragma unroll
        for (int ni = 0; ni < 8; ni++) {
            float p0 = __expf(s[ni][0] - mn0), p1 = __expf(s[ni][1] - mn0);
            float p2 = __expf(s[ni][2] - mn1), p3 = __expf(s[ni][3] - mn1);
            rs0 += p0 + p1; rs1 += p2 + p3;
            pp[ni][0] = pack_h2(make_float2(p0, p1));
            pp[ni][1] = pack_h2(make_float2(p2, p3));
        }
        rs0 += __shfl_xor_sync(0xffffffffu, rs0, 1);
        rs0 += __shfl_xor_sync(0xffffffffu, rs0, 2);
        rs1 += __shfl_xor_sync(0xffffffffu, rs1, 1);
        rs1 += __shfl_xor_sync(0xffffffffu, rs1, 2);
        l0 = l0 * sc0 + rs0; l1 = l1 * sc1 + rs1;
        m0 = mn0; m1 = mn1;
        #pragma unroll
        for (int ni = 0; ni < 8; ni++) {
            oacc[ni][0] *= sc0; oacc[ni][1] *= sc0;
            oacc[ni][2] *= sc1; oacc[ni][3] *= sc1;
        }

        // ---- O += P @ V ----
        #pragma unroll
        for (int ki = 0; ki < 4; ++ki) {
            uint32_t vko = (uint32_t)ki * 16 * FW * 4;
            uint32_t a[4] = { pp[2 * ki][0], pp[2 * ki][1],
                              pp[2 * ki + 1][0], pp[2 * ki + 1][1] };
            uint32_t bfr[8][2];
            #pragma unroll
            for (int pr = 0; pr < 4; pr++) {
                uint32_t t0, t1, t2, t3;
                LDSM4T(t0, t1, t2, t3, vbase + v_rel[pr] + vko);
                bfr[2 * pr][0] = t0; bfr[2 * pr][1] = t1;
                bfr[2 * pr + 1][0] = t2; bfr[2 * pr + 1][1] = t3;
            }
            #pragma unroll
            for (int ni = 0; ni < 8; ni++)
                mma_16n8k16_f16(oacc[ni], a, bfr[ni]);
        }
    }

    float inv0 = (l0 > 0.f) ? 1.f / l0 : 0.f;
    float inv1 = (l1 > 0.f) ? 1.f / l1 : 0.f;
    size_t ob0 = ((size_t)b * Sc + qi0) * Dc + h * DHc;
    size_t ob1 = ((size_t)b * Sc + qi1) * Dc + h * DHc;
    #pragma unroll
    for (int ni = 0; ni < 8; ni++) {
        int cc = ni * 8 + 2 * tg;
        *reinterpret_cast<uint32_t*>(&o[ob0 + cc]) =
            pack_h2(make_float2(oacc[ni][0] * inv0, oacc[ni][1] * inv0));
        *reinterpret_cast<uint32_t*>(&o[ob1 + cc]) =
            pack_h2(make_float2(oacc[ni][2] * inv1, oacc[ni][3] * inv1));
    }
}

// ---------------- embedding + PE (+ pad mask), dual fp32/fp16 output ----------------
__global__ void embed_pe_kernel(const int* __restrict__ toks,
                                const float* __restrict__ emb,
                                float* __restrict__ out,
                                __half* __restrict__ outh,
                                unsigned char* __restrict__ mask) {
    int pos = blockIdx.x % Sc;
    int b   = blockIdx.x / Sc;
    int tok = toks[b * Sc + pos];
    int t = threadIdx.x;
    if (t == 0) mask[b * Sc + pos] = (tok == 0) ? 1 : 0;
    const float c = -logf(10000.0f) / (float)Dc;
    size_t base = ((size_t)b * Sc + pos) * Dc;
    #pragma unroll
    for (int d = t; d < Dc; d += 256) {
        int i = d >> 1;
        float freq = __expf((float)(2 * i) * c);
        float ang  = (float)pos * freq;
        float pe   = (d & 1) ? cosf(ang) : sinf(ang);
        float v = emb[(size_t)tok * Dc + d] + pe;
        out[base + d] = v;
        outh[base + d] = __float2half_rn(v);
    }
}

// ---------------- LayerNorm: dual fp32 + fp16 output (warp per row) ----------------
__global__ void __launch_bounds__(256) ln_kernel(const float* __restrict__ xin,
                                                 const float* __restrict__ gamma,
                                                 const float* __restrict__ beta,
                                                 float* __restrict__ out,
                                                 __half* __restrict__ outh) {
    int warp = threadIdx.x >> 5, lane = threadIdx.x & 31;
    size_t row = (size_t)blockIdx.x * 8 + warp;
    size_t base = row * Dc;
    float4 v[4];
    float sum = 0.f;
    #pragma unroll
    for (int i = 0; i < 4; ++i) {
        v[i] = *reinterpret_cast<const float4*>(&xin[base + lane * 4 + i * 128]);
        sum += v[i].x + v[i].y + v[i].z + v[i].w;
    }
    #pragma unroll
    for (int s = 16; s > 0; s >>= 1) sum += __shfl_xor_sync(0xffffffffu, sum, s);
    float mu = sum * (1.0f / Dc);
    float var = 0.f;
    #pragma unroll
    for (int i = 0; i < 4; ++i) {
        v[i].x -= mu; v[i].y -= mu; v[i].z -= mu; v[i].w -= mu;
        var += v[i].x * v[i].x + v[i].y * v[i].y + v[i].z * v[i].z + v[i].w * v[i].w;
    }
    #pragma unroll
    for (int s = 16; s > 0; s >>= 1) var += __shfl_xor_sync(0xffffffffu, var, s);
    float inv = rsqrtf(var * (1.0f / Dc) + EPSc);
    #pragma unroll
    for (int i = 0; i < 4; ++i) {
        int col = lane * 4 + i * 128;
        float4 gv = *reinterpret_cast<const float4*>(&gamma[col]);
        float4 bv = *reinterpret_cast<const float4*>(&beta[col]);
        float4 o;
        o.x = v[i].x * inv * gv.x + bv.x;
        o.y = v[i].y * inv * gv.y + bv.y;
        o.z = v[i].z * inv * gv.z + bv.z;
        o.w = v[i].w * inv * gv.w + bv.w;
        *reinterpret_cast<float4*>(&out[base + col]) = o;
        uint2 hw = make_uint2(pack_h2(make_float2(o.x, o.y)),
                              pack_h2(make_float2(o.z, o.w)));
        *reinterpret_cast<uint2*>(&outh[base + col]) = hw;
    }
}

// ---------------- host orchestration ----------------
static void launch_gemm_f(const __half* A, const __half* BT, const float* bias,
                          const float* resid, float* C, int M, int N, int K) {
    dim3 grid(N / 128, M / 128);
    gemm_mma<false, false><<<grid, 256, GEMM_SMEM>>>(A, BT, bias, resid, C, M, N, K);
}
static void launch_gemm_h(const __half* A, const __half* BT, const float* bias,
                          __half* C, int M, int N, int K, bool relu) {
    dim3 grid(N / 128, M / 128);
    if (relu) gemm_mma<true,  true><<<grid, 256, GEMM_SMEM>>>(A, BT, bias, nullptr, C, M, N, K);
    else      gemm_mma<false, true><<<grid, 256, GEMM_SMEM>>>(A, BT, bias, nullptr, C, M, N, K);
}

extern "C" void kernel_launch(void* const* d_in, const int* in_sizes, int n_in,
                              void* d_out, int out_size) {
    const int*   inputs  = (const int*)d_in[0];
    const int*   outputs = (const int*)d_in[1];
    const float* emi = (const float*)d_in[2];
    const float* emo = (const float*)d_in[3];
    const float* enc_attn_w = (const float*)d_in[4];
    const float* enc_attn_b = (const float*)d_in[5];
    const float* enc_ln     = (const float*)d_in[6];
    const float* enc_ffn_w1 = (const float*)d_in[7];
    const float* enc_ffn_b1 = (const float*)d_in[8];
    const float* enc_ffn_w2 = (const float*)d_in[9];
    const float* enc_ffn_b2 = (const float*)d_in[10];
    const float* dec_self_w  = (const float*)d_in[11];
    const float* dec_self_b  = (const float*)d_in[12];
    const float* dec_cross_w = (const float*)d_in[13];
    const float* dec_cross_b = (const float*)d_in[14];
    const float* dec_ln      = (const float*)d_in[15];
    const float* dec_ffn_w1 = (const float*)d_in[16];
    const float* dec_ffn_b1 = (const float*)d_in[17];
    const float* dec_ffn_w2 = (const float*)d_in[18];
    const float* dec_ffn_b2 = (const float*)d_in[19];

    float *xp, *yp, *tmpp;
    __half *xh, *yh, *qkvh, *qh, *attnh, *hidh, *kvh;
    __half *wta_enc, *wta_self, *wta_cross, *wt_ef1, *wt_ef2, *wt_df1, *wt_df2;
    unsigned char *mxp, *myp;
    cudaGetSymbolAddress((void**)&xp, g_x);
    cudaGetSymbolAddress((void**)&yp, g_y);
    cudaGetSymbolAddress((void**)&tmpp, g_tmp);
    cudaGetSymbolAddress((void**)&xh, g_xh);
    cudaGetSymbolAddress((void**)&yh, g_yh);
    cudaGetSymbolAddress((void**)&qkvh, g_qkvh);
    cudaGetSymbolAddress((void**)&qh, g_qh);
    cudaGetSymbolAddress((void**)&attnh, g_attnh);
    cudaGetSymbolAddress((void**)&hidh, g_hidh);
    cudaGetSymbolAddress((void**)&kvh, g_kvh);
    cudaGetSymbolAddress((void**)&mxp, g_mx);
    cudaGetSymbolAddress((void**)&myp, g_my);
    cudaGetSymbolAddress((void**)&wta_enc,   g_wt_enc_attn);
    cudaGetSymbolAddress((void**)&wta_self,  g_wt_dec_self);
    cudaGetSymbolAddress((void**)&wta_cross, g_wt_dec_cross);
    cudaGetSymbolAddress((void**)&wt_ef1, g_wt_enc_f1);
    cudaGetSymbolAddress((void**)&wt_ef2, g_wt_enc_f2);
    cudaGetSymbolAddress((void**)&wt_df1, g_wt_dec_f1);
    cudaGetSymbolAddress((void**)&wt_df2, g_wt_dec_f2);

    cudaFuncSetAttribute(flash_attn, cudaFuncAttributeMaxDynamicSharedMemorySize, FLASH_SMEM);
    cudaFuncSetAttribute(gemm_mma<false, false>, cudaFuncAttributeMaxDynamicSharedMemorySize, GEMM_SMEM);
    cudaFuncSetAttribute(gemm_mma<false, true >, cudaFuncAttributeMaxDynamicSharedMemorySize, GEMM_SMEM);
    cudaFuncSetAttribute(gemm_mma<true,  true >, cudaFuncAttributeMaxDynamicSharedMemorySize, GEMM_SMEM);
    cudaFuncSetAttribute(gemm_kv_all, cudaFuncAttributeMaxDynamicSharedMemorySize, GEMM_SMEM);

    // -------- weight transposes (fp32 -> fp16, [N][K]) --------
    dim3 tblk(32, 8);
    transpose_h<<<dim3(Dc / 32, Dc / 32, Lc * 4), tblk>>>(enc_attn_w,  wta_enc,   Dc, Dc);
    transpose_h<<<dim3(Dc / 32, Dc / 32, Lc * 4), tblk>>>(dec_self_w,  wta_self,  Dc, Dc);
    transpose_h<<<dim3(Dc / 32, Dc / 32, Lc * 4), tblk>>>(dec_cross_w, wta_cross, Dc, Dc);
    transpose_h<<<dim3(HIDc / 32, Dc / 32, Lc), tblk>>>(enc_ffn_w1, wt_ef1, Dc, HIDc);
    transpose_h<<<dim3(Dc / 32, HIDc / 32, Lc), tblk>>>(enc_ffn_w2, wt_ef2, HIDc, Dc);
    transpose_h<<<dim3(HIDc / 32, Dc / 32, Lc), tblk>>>(dec_ffn_w1, wt_df1, Dc, HIDc);
    transpose_h<<<dim3(Dc / 32, HIDc / 32, Lc), tblk>>>(dec_ffn_w2, wt_df2, HIDc, Dc);

    dim3 blk(256);
    embed_pe_kernel<<<BSc, blk>>>(inputs,  emi, xp, xh, mxp);
    embed_pe_kernel<<<BSc, blk>>>(outputs, emo, yp, yh, myp);

    int lng = BSc / 8;
    dim3 gfl(Sc / 64, Bc * NHc);

    // ---------------- encoder ----------------
    for (int l = 0; l < Lc; ++l) {
        const __half* wT = wta_enc + (size_t)l * 4 * Dc * Dc;
        const float* ab = enc_attn_b + (size_t)l * 4 * Dc;
        launch_gemm_h(xh, wT, ab, qkvh, BSc, 3 * Dc, Dc, false);
        flash_attn<<<gfl, 128, FLASH_SMEM>>>(qkvh, 3 * Dc, qkvh + Dc, qkvh + 2 * Dc, 3 * Dc,
                                             mxp, mxp, attnh, 0);
        launch_gemm_f(attnh, wT + 3 * (size_t)Dc * Dc, ab + 3 * Dc, xp, tmpp, BSc, Dc, Dc);
        const float* ln0 = enc_ln + (((size_t)l * 2 + 0) * 2) * Dc;
        ln_kernel<<<lng, blk>>>(tmpp, ln0, ln0 + Dc, xp, xh);
        launch_gemm_h(xh, wt_ef1 + (size_t)l * Dc * HIDc, enc_ffn_b1 + (size_t)l * HIDc,
                      hidh, BSc, HIDc, Dc, true);
        launch_gemm_f(hidh, wt_ef2 + (size_t)l * Dc * HIDc, enc_ffn_b2 + (size_t)l * Dc,
                      xp, tmpp, BSc, Dc, HIDc);
        const float* ln1 = enc_ln + (((size_t)l * 2 + 1) * 2) * Dc;
        ln_kernel<<<lng, blk>>>(tmpp, ln1, ln1 + Dc, xp, xh);
    }

    // -------- all-layer cross KV projections, one batched launch --------
    {
        dim3 gkv(2 * Dc / 128, BSc / 128, Lc);
        gemm_kv_all<<<gkv, 256, GEMM_SMEM>>>(xh, wta_cross, dec_cross_b, kvh);
    }

    // ---------------- decoder ----------------
    float* fout = (float*)d_out;
    for (int l = 0; l < Lc; ++l) {
        const __half* swT = wta_self + (size_t)l * 4 * Dc * Dc;
        const float* sb  = dec_self_b + (size_t)l * 4 * Dc;
        launch_gemm_h(yh, swT, sb, qkvh, BSc, 3 * Dc, Dc, false);
        flash_attn<<<gfl, 128, FLASH_SMEM>>>(qkvh, 3 * Dc, qkvh + Dc, qkvh + 2 * Dc, 3 * Dc,
                                             myp, myp, attnh, 1);
        launch_gemm_f(attnh, swT + 3 * (size_t)Dc * Dc, sb + 3 * Dc, yp, tmpp, BSc, Dc, Dc);
        const float* ln0 = dec_ln + (((size_t)l * 3 + 0) * 2) * Dc;
        ln_kernel<<<lng, blk>>>(tmpp, ln0, ln0 + Dc, yp, yh);

        const __half* cwT = wta_cross + (size_t)l * 4 * Dc * Dc;
        const float* cb  = dec_cross_b + (size_t)l * 4 * Dc;
        __half* kv = kvh + (size_t)l * BSc * 2 * Dc;
        launch_gemm_h(yh, cwT, cb, qh, BSc, Dc, Dc, false);
        flash_attn<<<gfl, 128, FLASH_SMEM>>>(qh, Dc, kv, kv + Dc, 2 * Dc,
                                             myp, mxp, attnh, 0);
        launch_gemm_f(attnh, cwT + 3 * (size_t)Dc * Dc, cb + 3 * Dc, yp, tmpp, BSc, Dc, Dc);
        const float* ln1 = dec_ln + (((size_t)l * 3 + 1) * 2) * Dc;
        ln_kernel<<<lng, blk>>>(tmpp, ln1, ln1 + Dc, yp, yh);

        launch_gemm_h(yh, wt_df1 + (size_t)l * Dc * HIDc, dec_ffn_b1 + (size_t)l * HIDc,
                      hidh, BSc, HIDc, Dc, true);
        launch_gemm_f(hidh, wt_df2 + (size_t)l * Dc * HIDc, dec_ffn_b2 + (size_t)l * Dc,
                      yp, tmpp, BSc, Dc, HIDc);
        const float* ln2 = dec_ln + (((size_t)l * 3 + 2) * 2) * Dc;
        float* dst = (l == Lc - 1) ? fout : yp;
        ln_kernel<<<lng, blk>>>(tmpp, ln2, ln2 + Dc, dst, yh);
    }
    (void)in_sizes; (void)n_in; (void)out_size;
}